// round 8
// baseline (speedup 1.0000x reference)
#include <cuda_runtime.h>
#include <cuda_bf16.h>
#include <cstdint>

static constexpr int kNH = 50000;
static constexpr int kNO = 50000;
static constexpr int kE  = 500000;
static constexpr int kD  = 256;
static constexpr int kL  = 8;
static constexpr int kB  = 512;
static constexpr int kC  = 117;

// ---------------- device scratch (static, no runtime alloc) ----------------
__device__ float g_h0[kNH * kD];
__device__ float g_h1[kNH * kD];
__device__ float g_o0[kNO * kD];
__device__ float g_o1[kNO * kD];
__device__ float g_agg0[kNO * kD];
__device__ float g_agg1[kNH * kD];

// attention scalars: [aSho | aDoh | aDho | aSoh]
__device__ float g_avec[4 * kNH];

__device__ float g_vsrc[2 * kL * kD];
__device__ float g_vdst[2 * kL * kD];
__device__ float g_cedge[2 * kL * 2];

// W^T as bf16 hi/lo: [rel*8+layer][hi/lo][n=256][k=256]
__device__ __nv_bfloat16 g_wTb[2 * kL * 2 * kD * kD];

static constexpr int SCHUNK = 4096;
static constexpr int NCHUNK = (kNH + SCHUNK - 1) / SCHUNK;  // 13

__device__ int g_off[2 * (kNH + 1)];
__device__ int g_eid[2 * kE];
__device__ int g_cursor[2 * kNH];
__device__ int g_part[2 * NCHUNK];

// pooling buffers, one contiguous block: hsum | osum | esum | hcnt | ocnt | ecnt
static constexpr int POOLN = 2 * kB * kD + kB * 32 + 3 * kB;
__device__ float g_pool[POOLN];

__device__ __forceinline__ uint32_t pack2(__nv_bfloat16 a, __nv_bfloat16 b) {
    return (uint32_t)__bfloat16_as_ushort(a) | ((uint32_t)__bfloat16_as_ushort(b) << 16);
}

// ============================================================================
// small precompute
// ============================================================================
__global__ void k_precompute(
    const float* __restrict__ Wsrc0, const float* __restrict__ asrc0,
    const float* __restrict__ Wdst0, const float* __restrict__ adst0,
    const float* __restrict__ Wedge0, const float* __restrict__ aedge0,
    const float* __restrict__ Wsrc1, const float* __restrict__ asrc1,
    const float* __restrict__ Wdst1, const float* __restrict__ adst1,
    const float* __restrict__ Wedge1, const float* __restrict__ aedge1)
{
    int rel = blockIdx.x / kL;
    int l   = blockIdx.x % kL;
    const float* Wsrc  = rel ? Wsrc1  : Wsrc0;
    const float* asrc  = rel ? asrc1  : asrc0;
    const float* Wdst  = rel ? Wdst1  : Wdst0;
    const float* adst  = rel ? adst1  : adst0;
    const float* Wedge = rel ? Wedge1 : Wedge0;
    const float* aedge = rel ? aedge1 : aedge0;

    int i = threadIdx.x;
    float s1 = 0.f, s2 = 0.f;
    const float* wsr = Wsrc + (long)l * kD * kD + (long)i * kD;
    const float* wdr = Wdst + (long)l * kD * kD + (long)i * kD;
    const float* as  = asrc + l * kD;
    const float* ad  = adst + l * kD;
    for (int j = 0; j < kD; j++) { s1 += wsr[j] * as[j]; s2 += wdr[j] * ad[j]; }
    g_vsrc[(rel * kL + l) * kD + i] = s1;
    g_vdst[(rel * kL + l) * kD + i] = s2;
    if (i < 2) {
        float c = 0.f;
        const float* we = Wedge + (long)l * 2 * kD + (long)i * kD;
        const float* ae = aedge + l * kD;
        for (int j = 0; j < kD; j++) c += we[j] * ae[j];
        g_cedge[(rel * kL + l) * 2 + i] = c;
    }
}

// ---------------- transpose + bf16 hi/lo split of Wsrc weights ----------------
__global__ void k_wprep(const float* __restrict__ W_ho, const float* __restrict__ W_oh)
{
    int rl = blockIdx.x;
    int rel = rl >> 3;
    const float* W = (rel ? W_oh : W_ho) + (long)(rl & 7) * kD * kD;
    int tile = blockIdx.y;
    int tk = (tile & 7) * 32, tn = (tile >> 3) * 32;
    __shared__ float s[32][33];
    int tx = threadIdx.x, ty = threadIdx.y;
    for (int yy = ty; yy < 32; yy += 8)
        s[yy][tx] = W[(long)(tk + yy) * kD + tn + tx];
    __syncthreads();
    __nv_bfloat16* outHi = g_wTb + (long)rl * 2 * kD * kD;
    __nv_bfloat16* outLo = outHi + kD * kD;
    for (int yy = ty; yy < 32; yy += 8) {
        float v = s[tx][yy];
        __nv_bfloat16 h = __float2bfloat16(v);
        __nv_bfloat16 l = __float2bfloat16(v - __bfloat162float(h));
        outHi[(long)(tn + yy) * kD + tk + tx] = h;
        outLo[(long)(tn + yy) * kD + tk + tx] = l;
    }
}

// ---------------- CSR build (dual-relation) ----------------
__global__ void k_hist(const int* __restrict__ d0, const int* __restrict__ d1,
                       int* __restrict__ cnt)
{
    int e = blockIdx.x * blockDim.x + threadIdx.x;
    if (e >= kE) return;
    int rel = blockIdx.y;
    const int* d = rel ? d1 : d0;
    atomicAdd(&cnt[rel * kNH + d[e]], 1);
}

__global__ void k_scan_part(const int* __restrict__ cnt, int* __restrict__ part)
{
    int rel = blockIdx.y, ch = blockIdx.x;
    const int* c = cnt + rel * kNH + ch * SCHUNK;
    int n = min(SCHUNK, kNH - ch * SCHUNK);
    int t = threadIdx.x, lane = t & 31, wid = t >> 5;
    int s = 0;
    for (int i = t; i < n; i += 256) s += c[i];
#pragma unroll
    for (int o = 16; o > 0; o >>= 1) s += __shfl_xor_sync(0xffffffffu, s, o);
    __shared__ int ws[8];
    if (lane == 0) ws[wid] = s;
    __syncthreads();
    if (t == 0) {
        int tot = 0;
        for (int k = 0; k < 8; k++) tot += ws[k];
        part[rel * NCHUNK + ch] = tot;
    }
}

__global__ void k_scan_mid(int* __restrict__ part)
{
    int rel = threadIdx.x;
    if (rel < 2) {
        int run = 0;
        for (int i = 0; i < NCHUNK; i++) {
            int v = part[rel * NCHUNK + i];
            part[rel * NCHUNK + i] = run;
            run += v;
        }
    }
}

__global__ void k_scan_apply(int* __restrict__ cnt, int* __restrict__ off,
                             const int* __restrict__ part)
{
    int rel = blockIdx.y, ch = blockIdx.x;
    int* cc = cnt + rel * kNH;
    int* oo = off + rel * (kNH + 1);
    int start = ch * SCHUNK;
    int n = min(SCHUNK, kNH - start);
    int t = threadIdx.x, lane = t & 31, wid = t >> 5;
    __shared__ int wsum[8];
    int carry = part[rel * NCHUNK + ch];
    for (int b0 = 0; b0 < n; b0 += 256) {
        int i = start + b0 + t;
        int c = (b0 + t < n) ? cc[i] : 0;
        int v = c;
#pragma unroll
        for (int o = 1; o < 32; o <<= 1) {
            int u = __shfl_up_sync(0xffffffffu, v, o);
            if (lane >= o) v += u;
        }
        if (lane == 31) wsum[wid] = v;
        __syncthreads();
        int wpre = 0, btot = 0;
#pragma unroll
        for (int k = 0; k < 8; k++) {
            int ws = wsum[k];
            if (k < wid) wpre += ws;
            btot += ws;
        }
        int excl = carry + (v - c) + wpre;
        if (b0 + t < n) { oo[i] = excl; cc[i] = excl; }
        carry += btot;
        __syncthreads();
    }
    if (t == 0 && ch == 0) oo[kNH] = kE;
}

__global__ void k_scatter(const int* __restrict__ d0, const int* __restrict__ d1,
                          int* __restrict__ cur, int* __restrict__ eid)
{
    int e = blockIdx.x * blockDim.x + threadIdx.x;
    if (e >= kE) return;
    int rel = blockIdx.y;
    const int* d = rel ? d1 : d0;
    int p = atomicAdd(&cur[rel * kNH + d[e]], 1);
    eid[rel * kE + p] = e;
}

// ---------------- fused dual matvec (layer 0 only) ----------------
__global__ void k_matvec2_dual(const float* __restrict__ xh, const float* __restrict__ xo,
                               const float* __restrict__ vh1, const float* __restrict__ vh2,
                               const float* __restrict__ vo1, const float* __restrict__ vo2,
                               float* __restrict__ avec)
{
    int gw = (blockIdx.x * blockDim.x + threadIdx.x) >> 5;
    int lane = threadIdx.x & 31;
    if (gw >= kNH + kNO) return;
    int rel = gw >= kNH;
    int w = rel ? gw - kNH : gw;
    const float* x  = rel ? xo  : xh;
    const float* v1 = rel ? vo1 : vh1;
    const float* v2 = rel ? vo2 : vh2;
    float* o1 = avec + (rel ? 2 * kNH : 0);          // aDho : aSho
    float* o2 = avec + (rel ? 3 * kNH : kNH);        // aSoh : aDoh

    const float* xr = x + (long)w * kD;
    float s1 = 0.f, s2 = 0.f;
#pragma unroll
    for (int k = 0; k < 8; k++) {
        float xv = xr[lane + 32 * k];
        s1 += xv * v1[lane + 32 * k];
        s2 += xv * v2[lane + 32 * k];
    }
#pragma unroll
    for (int o = 16; o > 0; o >>= 1) {
        s1 += __shfl_xor_sync(0xffffffffu, s1, o);
        s2 += __shfl_xor_sync(0xffffffffu, s2, o);
    }
    if (lane == 0) { o1[w] = s1; o2[w] = s2; }
}

// ---------------- dual per-dst segment softmax + weighted gather-aggregate ----------------
__global__ void k_aggregate_dual(
    const int* __restrict__ off, const int* __restrict__ eid,
    const int* __restrict__ src0, const float* __restrict__ ea0,
    const float* __restrict__ x0, const float* __restrict__ ced0, float* __restrict__ agg0,
    const int* __restrict__ src1, const float* __restrict__ ea1,
    const float* __restrict__ x1, const float* __restrict__ ced1, float* __restrict__ agg1,
    const float* __restrict__ avec)
{
    int gw = (blockIdx.x * blockDim.x + threadIdx.x) >> 5;
    int lane = threadIdx.x & 31;
    if (gw >= kNO + kNH) return;
    int rel = gw >= kNO;
    int w = rel ? gw - kNO : gw;
    const int* o    = off + rel * (kNH + 1);
    const int* ei   = eid + rel * kE;
    const int* src  = rel ? src1 : src0;
    const float* ea = rel ? ea1 : ea0;
    const float* aS = avec + (rel ? 3 * kNH : 0);    // aSoh : aSho
    const float* aD = avec + (rel ? kNH : 2 * kNH);  // aDoh : aDho
    const float* x  = rel ? x1 : x0;
    const float* ced = rel ? ced1 : ced0;
    float* agg = rel ? agg1 : agg0;

    int beg = o[w], end = o[w + 1];
    float c0 = ced[0], c1 = ced[1];
    float ad = aD[w];

    // online softmax: single pass for (max, denom)
    float m = -3.0e38f, den = 0.f;
    for (int i = beg + lane; i < end; i += 32) {
        int e = ei[i];
        float lg = aS[src[e]] + ad + c0 * ea[2 * e] + c1 * ea[2 * e + 1];
        lg = lg > 0.f ? lg : 0.2f * lg;
        float mn = fmaxf(m, lg);
        den = den * expf(m - mn) + expf(lg - mn);
        m = mn;
    }
#pragma unroll
    for (int o2 = 16; o2 > 0; o2 >>= 1) {
        float mo = __shfl_xor_sync(0xffffffffu, m, o2);
        float do_ = __shfl_xor_sync(0xffffffffu, den, o2);
        float mn = fmaxf(m, mo);
        den = den * expf(m - mn) + do_ * expf(mo - mn);
        m = mn;
    }

    float inv = (den > 0.f) ? 1.f / den : 0.f;
    float acc[8] = {0.f, 0.f, 0.f, 0.f, 0.f, 0.f, 0.f, 0.f};
    int i = beg;
    for (; i + 1 < end; i += 2) {
        int e0 = ei[i], e1 = ei[i + 1];
        int s0 = src[e0], s1 = src[e1];
        float g0 = aS[s0] + ad + c0 * ea[2 * e0] + c1 * ea[2 * e0 + 1];
        float g1 = aS[s1] + ad + c0 * ea[2 * e1] + c1 * ea[2 * e1 + 1];
        g0 = g0 > 0.f ? g0 : 0.2f * g0;
        g1 = g1 > 0.f ? g1 : 0.2f * g1;
        float w0 = expf(g0 - m) * inv;
        float w1 = expf(g1 - m) * inv;
        const float* xr0 = x + (long)s0 * kD;
        const float* xr1 = x + (long)s1 * kD;
#pragma unroll
        for (int k = 0; k < 8; k++) {
            acc[k] += w0 * xr0[lane + 32 * k];
            acc[k] += w1 * xr1[lane + 32 * k];
        }
    }
    if (i < end) {
        int e0 = ei[i];
        int s0 = src[e0];
        float g0 = aS[s0] + ad + c0 * ea[2 * e0] + c1 * ea[2 * e0 + 1];
        g0 = g0 > 0.f ? g0 : 0.2f * g0;
        float w0 = expf(g0 - m) * inv;
        const float* xr0 = x + (long)s0 * kD;
#pragma unroll
        for (int k = 0; k < 8; k++) acc[k] += w0 * xr0[lane + 32 * k];
    }
    float* ar = agg + (long)w * kD;
#pragma unroll
    for (int k = 0; k < 8; k++) ar[lane + 32 * k] = acc[k];
}

// ============================================================================
// mma.sync bf16 GEMM (3xBF16) + fused next-layer matvec in epilogue
// ============================================================================
static constexpr int HSTRIDE = 40;
static constexpr int GEMM_SMEM = 4 * 128 * HSTRIDE * 2;  // 40960 B

__device__ __forceinline__ void mma_bf16(float* c, const uint32_t* a, const uint32_t* b) {
    asm volatile(
        "mma.sync.aligned.m16n8k16.row.col.f32.bf16.bf16.f32 "
        "{%0,%1,%2,%3}, {%4,%5,%6,%7}, {%8,%9}, {%0,%1,%2,%3};\n"
        : "+f"(c[0]), "+f"(c[1]), "+f"(c[2]), "+f"(c[3])
        : "r"(a[0]), "r"(a[1]), "r"(a[2]), "r"(a[3]), "r"(b[0]), "r"(b[1]));
}

__global__ void __launch_bounds__(512) k_gemm_mma(
    const float* __restrict__ A0, const float* __restrict__ A1,
    const __nv_bfloat16* __restrict__ WT0, const __nv_bfloat16* __restrict__ WT1,
    const float* __restrict__ bias0, const float* __restrict__ bias1,
    const float* __restrict__ prev0, const float* __restrict__ prev1,
    float* __restrict__ out0, float* __restrict__ out1, int M,
    // next-layer matvec fusion: z=0 (objects): vecs (vdst_ho, vsrc_oh) -> avec[2],avec[3]
    //                            z=1 (humans):  vecs (vsrc_ho, vdst_oh) -> avec[0],avec[1]
    const float* __restrict__ vz0a, const float* __restrict__ vz0b,
    const float* __restrict__ vz1a, const float* __restrict__ vz1b,
    float* __restrict__ avec, int doVec)
{
    extern __shared__ __nv_bfloat16 smh[];
    __nv_bfloat16* sAhi = smh;
    __nv_bfloat16* sAlo = smh + 128 * HSTRIDE;
    __nv_bfloat16* sBhi = smh + 2 * 128 * HSTRIDE;
    __nv_bfloat16* sBlo = smh + 3 * 128 * HSTRIDE;

    const int z = blockIdx.z;
    const float* A = z ? A1 : A0;
    const __nv_bfloat16* WT = z ? WT1 : WT0;
    const float* bias = z ? bias1 : bias0;
    const float* prev = z ? prev1 : prev0;
    float* out = z ? out1 : out0;
    const float* vec1 = z ? vz1a : vz0a;
    const float* vec2 = z ? vz1b : vz0b;
    float* av1 = avec + (z ? 0 : 2 * kNH);
    float* av2 = avec + (z ? kNH : 3 * kNH);

    const int tid = threadIdx.x;
    const int w = tid >> 5, lane = tid & 31;
    const int wm = w & 3, wn = w >> 2;
    const int grp = lane >> 2, qt = lane & 3;
    const int mBase = blockIdx.y * 128;
    const int nBase = blockIdx.x * 128;

    const __nv_bfloat16* WThi = WT + (long)nBase * kD;
    const __nv_bfloat16* WTlo = WT + (long)kD * kD + (long)nBase * kD;

    float acc[2][4][4];
#pragma unroll
    for (int i = 0; i < 2; i++)
#pragma unroll
        for (int j = 0; j < 4; j++)
#pragma unroll
            for (int q = 0; q < 4; q++) acc[i][j][q] = 0.f;

    for (int c = 0; c < 8; c++) {
#pragma unroll
        for (int it = 0; it < 2; it++) {
            int idx = tid + it * 512;
            int r = idx >> 3, q = idx & 7;
            int gm = mBase + r;
            float4 v = (gm < M) ? *(const float4*)&A[(long)gm * kD + c * 32 + q * 4]
                                : make_float4(0.f, 0.f, 0.f, 0.f);
            __nv_bfloat16 hx = __float2bfloat16(v.x), hy = __float2bfloat16(v.y);
            __nv_bfloat16 hz = __float2bfloat16(v.z), hw = __float2bfloat16(v.w);
            __nv_bfloat16 lx = __float2bfloat16(v.x - __bfloat162float(hx));
            __nv_bfloat16 ly = __float2bfloat16(v.y - __bfloat162float(hy));
            __nv_bfloat16 lz = __float2bfloat16(v.z - __bfloat162float(hz));
            __nv_bfloat16 lw = __float2bfloat16(v.w - __bfloat162float(hw));
            uint2 hv, lv;
            hv.x = pack2(hx, hy); hv.y = pack2(hz, hw);
            lv.x = pack2(lx, ly); lv.y = pack2(lz, lw);
            *(uint2*)&sAhi[r * HSTRIDE + q * 4] = hv;
            *(uint2*)&sAlo[r * HSTRIDE + q * 4] = lv;
        }
#pragma unroll
        for (int it = 0; it < 2; it++) {
            int idx = tid + it * 512;
            int n = idx >> 3, q = idx & 7;
            *(uint2*)&sBhi[n * HSTRIDE + q * 4] =
                *(const uint2*)&WThi[(long)n * kD + c * 32 + q * 4];
            *(uint2*)&sBlo[n * HSTRIDE + q * 4] =
                *(const uint2*)&WTlo[(long)n * kD + c * 32 + q * 4];
        }
        __syncthreads();

#pragma unroll
        for (int ks = 0; ks < 2; ks++) {
            int kb = ks * 16;
            uint32_t ahi[2][4], alo[2][4], bhi[4][2], blo[4][2];
#pragma unroll
            for (int i = 0; i < 2; i++) {
                int ra = (wm * 32 + i * 16 + grp) * HSTRIDE + kb + qt * 2;
                ahi[i][0] = *(const uint32_t*)&sAhi[ra];
                ahi[i][1] = *(const uint32_t*)&sAhi[ra + 8 * HSTRIDE];
                ahi[i][2] = *(const uint32_t*)&sAhi[ra + 8];
                ahi[i][3] = *(const uint32_t*)&sAhi[ra + 8 * HSTRIDE + 8];
                alo[i][0] = *(const uint32_t*)&sAlo[ra];
                alo[i][1] = *(const uint32_t*)&sAlo[ra + 8 * HSTRIDE];
                alo[i][2] = *(const uint32_t*)&sAlo[ra + 8];
                alo[i][3] = *(const uint32_t*)&sAlo[ra + 8 * HSTRIDE + 8];
            }
#pragma unroll
            for (int j = 0; j < 4; j++) {
                int rb = (wn * 32 + j * 8 + grp) * HSTRIDE + kb + qt * 2;
                bhi[j][0] = *(const uint32_t*)&sBhi[rb];
                bhi[j][1] = *(const uint32_t*)&sBhi[rb + 8];
                blo[j][0] = *(const uint32_t*)&sBlo[rb];
                blo[j][1] = *(const uint32_t*)&sBlo[rb + 8];
            }
#pragma unroll
            for (int i = 0; i < 2; i++)
#pragma unroll
                for (int j = 0; j < 4; j++) {
                    mma_bf16(acc[i][j], ahi[i], bhi[j]);
                    mma_bf16(acc[i][j], ahi[i], blo[j]);
                    mma_bf16(acc[i][j], alo[i], bhi[j]);
                }
        }
        __syncthreads();
    }

    // epilogue + fused matvec for next layer
    float v1c[8], v2c[8];
    if (doVec) {
#pragma unroll
        for (int j = 0; j < 4; j++) {
            int col = nBase + wn * 32 + j * 8 + qt * 2;
            v1c[2 * j] = vec1[col]; v1c[2 * j + 1] = vec1[col + 1];
            v2c[2 * j] = vec2[col]; v2c[2 * j + 1] = vec2[col + 1];
        }
    }
#pragma unroll
    for (int i = 0; i < 2; i++) {
#pragma unroll
        for (int h = 0; h < 2; h++) {
            int row = mBase + wm * 32 + i * 16 + grp + h * 8;
            bool valid = row < M;
            float sv1 = 0.f, sv2 = 0.f;
#pragma unroll
            for (int j = 0; j < 4; j++) {
                int col = nBase + wn * 32 + j * 8 + qt * 2;
                float v0 = acc[i][j][h * 2 + 0] + bias[col];
                float v1 = acc[i][j][h * 2 + 1] + bias[col + 1];
                v0 = fmaxf(v0, 0.f);
                v1 = fmaxf(v1, 0.f);
                if (prev && valid) {
                    float2 pv = *(const float2*)&prev[(long)row * kD + col];
                    v0 += pv.x; v1 += pv.y;
                }
                if (valid) {
                    float2 o; o.x = v0; o.y = v1;
                    *(float2*)&out[(long)row * kD + col] = o;
                }
                if (doVec) {
                    sv1 += v0 * v1c[2 * j] + v1 * v1c[2 * j + 1];
                    sv2 += v0 * v2c[2 * j] + v1 * v2c[2 * j + 1];
                }
            }
            if (doVec) {
                // reduce over qt (lane bits 0,1); all 4 quad lanes share `row`
                sv1 += __shfl_xor_sync(0xffffffffu, sv1, 1);
                sv1 += __shfl_xor_sync(0xffffffffu, sv1, 2);
                sv2 += __shfl_xor_sync(0xffffffffu, sv2, 1);
                sv2 += __shfl_xor_sync(0xffffffffu, sv2, 2);
                if (qt == 0 && valid) {
                    atomicAdd(&av1[row], sv1);
                    atomicAdd(&av2[row], sv2);
                }
            }
        }
    }
}

// ---------------- pooling: segmented reduction over sorted batch ids ----------------
static constexpr int PCH = 512;
__global__ void k_pool_nodes(const float* __restrict__ x, const int* __restrict__ batch,
                             float* __restrict__ sum, float* __restrict__ cnt, int N)
{
    int n0 = blockIdx.x * PCH;
    int n1 = min(N, n0 + PCH);
    int d = threadIdx.x;
    float acc = 0.f;
    int curb = __ldg(&batch[n0]);
    for (int n = n0; n < n1; n++) {
        int b = __ldg(&batch[n]);
        if (b != curb) {
            atomicAdd(&sum[curb * kD + d], acc);
            acc = 0.f;
            curb = b;
        }
        acc += x[(long)n * kD + d];
    }
    atomicAdd(&sum[curb * kD + d], acc);
    if (d == 0) {
        int c = 0;
        curb = __ldg(&batch[n0]);
        for (int n = n0; n < n1; n++) {
            int b = __ldg(&batch[n]);
            if (b != curb) { atomicAdd(&cnt[curb], (float)c); c = 0; curb = b; }
            c++;
        }
        atomicAdd(&cnt[curb], (float)c);
    }
}

__global__ void k_pool_edges(const float* __restrict__ ea, const int* __restrict__ src,
                             const int* __restrict__ hbatch,
                             const float* __restrict__ Wm, const float* __restrict__ bm,
                             float* __restrict__ esum, float* __restrict__ ecnt)
{
    int e = blockIdx.x * blockDim.x + threadIdx.x;
    if (e >= kE) return;
    float e0 = ea[2 * e], e1 = ea[2 * e + 1];
    int b = hbatch[src[e]];
    atomicAdd(&ecnt[b], 1.f);
#pragma unroll
    for (int j = 0; j < 32; j++) {
        float v = fmaxf(e0 * Wm[j] + e1 * Wm[32 + j] + bm[j], 0.f);
        atomicAdd(&esum[b * 32 + j], v);
    }
}

// ---------------- final: graph emb -> 2 softmax heads ----------------
__global__ void k_final(const float* __restrict__ pool,
                        const float* __restrict__ Wp1, const float* __restrict__ bp1,
                        const float* __restrict__ Wp2, const float* __restrict__ bp2,
                        float* __restrict__ out)
{
    const float* hsum = pool;
    const float* osum = pool + kB * kD;
    const float* esum = pool + 2 * kB * kD;
    const float* hcnt = pool + 2 * kB * kD + kB * 32;
    const float* ocnt = hcnt + kB;
    const float* ecnt = ocnt + kB;

    __shared__ float emb[2 * kD + 32];
    __shared__ float red[128];
    int b = blockIdx.x, t = threadIdx.x;
    float hc = fmaxf(hcnt[b], 1.f), oc = fmaxf(ocnt[b], 1.f), ec = fmaxf(ecnt[b], 1.f);
    for (int k = t; k < kD; k += 128) {
        emb[k]      = hsum[b * kD + k] / hc;
        emb[kD + k] = osum[b * kD + k] / oc;
    }
    for (int k = t; k < 32; k += 128) emb[2 * kD + k] = esum[b * 32 + k] / ec;
    __syncthreads();

    for (int head = 0; head < 2; head++) {
        const float* W  = head ? Wp2 : Wp1;
        const float* bb = head ? bp2 : bp1;
        float v = -3.0e38f;
        if (t < kC) {
            v = bb[t];
            for (int k = 0; k < 2 * kD + 32; k++) v += emb[k] * W[k * kC + t];
        }
        red[t] = v;
        __syncthreads();
        for (int s = 64; s > 0; s >>= 1) {
            if (t < s) red[t] = fmaxf(red[t], red[t + s]);
            __syncthreads();
        }
        float mx = red[0];
        __syncthreads();
        float ex = (t < kC) ? expf(v - mx) : 0.f;
        red[t] = ex;
        __syncthreads();
        for (int s = 64; s > 0; s >>= 1) {
            if (t < s) red[t] += red[t + s];
            __syncthreads();
        }
        float sm = red[0];
        __syncthreads();
        if (t < kC) out[(b * 2 + head) * kC + t] = ex / sm;
    }
}

// ---------------- launch ----------------
extern "C" void kernel_launch(void* const* d_in, const int* in_sizes, int n_in,
                              void* d_out, int out_size)
{
    const float* x_human = (const float*)d_in[0];
    const float* x_object = (const float*)d_in[1];
    const int* ei_ho = (const int*)d_in[2];
    const int* ei_oh = (const int*)d_in[3];
    const float* ea_ho = (const float*)d_in[4];
    const float* ea_oh = (const float*)d_in[5];
    const int* hbatch = (const int*)d_in[6];
    const int* obatch = (const int*)d_in[7];
    const float* Wsrc_ho = (const float*)d_in[8];
    const float* Wdst_ho = (const float*)d_in[9];
    const float* asrc_ho = (const float*)d_in[10];
    const float* adst_ho = (const float*)d_in[11];
    const float* Wedge_ho = (const float*)d_in[12];
    const float* aedge_ho = (const float*)d_in[13];
    const float* bias_ho = (const float*)d_in[14];
    const float* Wsrc_oh = (const float*)d_in[15];
    const float* Wdst_oh = (const float*)d_in[16];
    const float* asrc_oh = (const float*)d_in[17];
    const float* adst_oh = (const float*)d_in[18];
    const float* Wedge_oh = (const float*)d_in[19];
    const float* aedge_oh = (const float*)d_in[20];
    const float* bias_oh = (const float*)d_in[21];
    const float* W_emlp = (const float*)d_in[22];
    const float* b_emlp = (const float*)d_in[23];
    const float* W_p1 = (const float*)d_in[24];
    const float* b_p1 = (const float*)d_in[25];
    const float* W_p2 = (const float*)d_in[26];
    const float* b_p2 = (const float*)d_in[27];

    float *h0, *h1, *o0, *o1, *agg0, *agg1, *avec;
    float *vsrc, *vdst, *ced, *pool;
    __nv_bfloat16* wTb;
    int *off, *eid, *cur, *part;
    cudaGetSymbolAddress((void**)&h0, g_h0);
    cudaGetSymbolAddress((void**)&h1, g_h1);
    cudaGetSymbolAddress((void**)&o0, g_o0);
    cudaGetSymbolAddress((void**)&o1, g_o1);
    cudaGetSymbolAddress((void**)&agg0, g_agg0);
    cudaGetSymbolAddress((void**)&agg1, g_agg1);
    cudaGetSymbolAddress((void**)&avec, g_avec);
    cudaGetSymbolAddress((void**)&vsrc, g_vsrc);
    cudaGetSymbolAddress((void**)&vdst, g_vdst);
    cudaGetSymbolAddress((void**)&ced, g_cedge);
    cudaGetSymbolAddress((void**)&wTb, g_wTb);
    cudaGetSymbolAddress((void**)&off, g_off);
    cudaGetSymbolAddress((void**)&eid, g_eid);
    cudaGetSymbolAddress((void**)&cur, g_cursor);
    cudaGetSymbolAddress((void**)&part, g_part);
    cudaGetSymbolAddress((void**)&pool, g_pool);

    cudaFuncSetAttribute(k_gemm_mma, cudaFuncAttributeMaxDynamicSharedMemorySize, GEMM_SMEM);

    const int EB = (kE + 255) / 256;
    const dim3 GEMM_GRID(2, (kNH + 127) / 128, 2);

    // ---- CSR build for both relations ----
    cudaMemsetAsync(cur, 0, sizeof(int) * 2 * kNH);
    k_hist<<<dim3(EB, 2), 256>>>(ei_ho + kE, ei_oh + kE, cur);
    k_scan_part<<<dim3(NCHUNK, 2), 256>>>(cur, part);
    k_scan_mid<<<1, 32>>>(part);
    k_scan_apply<<<dim3(NCHUNK, 2), 256>>>(cur, off, part);
    k_scatter<<<dim3(EB, 2), 256>>>(ei_ho + kE, ei_oh + kE, cur, eid);

    // ---- per-layer precompute ----
    k_precompute<<<2 * kL, 256>>>(Wsrc_ho, asrc_ho, Wdst_ho, adst_ho, Wedge_ho, aedge_ho,
                                  Wsrc_oh, asrc_oh, Wdst_oh, adst_oh, Wedge_oh, aedge_oh);
    k_wprep<<<dim3(16, 64), dim3(32, 8)>>>(Wsrc_ho, Wsrc_oh);

    // ---- 8 layers ----
    const float* cur_h = x_human;
    const float* cur_o = x_object;
    for (int l = 0; l < kL; l++) {
        float* nh = (l & 1) ? h1 : h0;
        float* no = (l & 1) ? o1 : o0;

        if (l == 0) {
            k_matvec2_dual<<<(kNH + kNO) / 8, 256>>>(
                cur_h, cur_o,
                vsrc + (0 * kL + l) * kD, vdst + (1 * kL + l) * kD,
                vdst + (0 * kL + l) * kD, vsrc + (1 * kL + l) * kD,
                avec);
        }

        k_aggregate_dual<<<(kNO + kNH) / 8, 256>>>(
            off, eid,
            ei_ho, ea_ho, cur_h, ced + (0 * kL + l) * 2, agg0,
            ei_oh, ea_oh, cur_o, ced + (1 * kL + l) * 2, agg1,
            avec);

        int doVec = (l + 1 < kL);
        if (doVec) cudaMemsetAsync(avec, 0, sizeof(float) * 4 * kNH);

        int ln = l + 1 < kL ? l + 1 : l;  // vec pointers (unused when doVec=0)
        k_gemm_mma<<<GEMM_GRID, 512, GEMM_SMEM>>>(
            agg0, agg1,
            wTb + (long)(0 * kL + l) * 2 * kD * kD, wTb + (long)(1 * kL + l) * 2 * kD * kD,
            bias_ho + l * kD, bias_oh + l * kD,
            l ? cur_o : nullptr, l ? cur_h : nullptr,
            no, nh, kNO,
            vdst + (0 * kL + ln) * kD, vsrc + (1 * kL + ln) * kD,   // z=0: objects
            vsrc + (0 * kL + ln) * kD, vdst + (1 * kL + ln) * kD,   // z=1: humans
            avec, doVec);

        cur_h = nh;
        cur_o = no;
    }

    // ---- pooling ----
    cudaMemsetAsync(pool, 0, sizeof(float) * POOLN);
    float* hsum = pool;
    float* osum = pool + kB * kD;
    float* esum = pool + 2 * kB * kD;
    float* hcnt = pool + 2 * kB * kD + kB * 32;
    float* ocnt = hcnt + kB;
    float* ecnt = ocnt + kB;
    k_pool_nodes<<<(kNH + PCH - 1) / PCH, 256>>>(cur_h, hbatch, hsum, hcnt, kNH);
    k_pool_nodes<<<(kNO + PCH - 1) / PCH, 256>>>(cur_o, obatch, osum, ocnt, kNO);
    k_pool_edges<<<EB, 256>>>(ea_ho, ei_ho, hbatch, W_emlp, b_emlp, esum, ecnt);

    // ---- classifier heads ----
    k_final<<<kB, 128>>>(pool, W_p1, b_p1, W_p2, b_p2, (float*)d_out);
}

// round 9
// speedup vs baseline: 1.5384x; 1.5384x over previous
#include <cuda_runtime.h>
#include <cuda_bf16.h>
#include <cstdint>

static constexpr int kNH = 50000;
static constexpr int kNO = 50000;
static constexpr int kE  = 500000;
static constexpr int kD  = 256;
static constexpr int kL  = 8;
static constexpr int kB  = 512;
static constexpr int kC  = 117;

// ---------------- device scratch (static, no runtime alloc) ----------------
__device__ float g_h0[kNH * kD];
__device__ float g_h1[kNH * kD];
__device__ float g_o0[kNO * kD];
__device__ float g_o1[kNO * kD];
__device__ float g_agg0[kNO * kD];
__device__ float g_agg1[kNH * kD];

__device__ float g_aSho[kNH], g_aDoh[kNH], g_aDho[kNO], g_aSoh[kNO];

__device__ float g_vsrc[2 * kL * kD];
__device__ float g_vdst[2 * kL * kD];
__device__ float g_cedge[2 * kL * 2];

// W^T as bf16 hi/lo: [rel*8+layer][hi/lo][n=256][k=256]
__device__ __nv_bfloat16 g_wTb[2 * kL * 2 * kD * kD];

static constexpr int SCHUNK = 4096;
static constexpr int NCHUNK = (kNH + SCHUNK - 1) / SCHUNK;  // 13

__device__ int g_off[2 * (kNH + 1)];
__device__ int g_eid[2 * kE];
__device__ int g_cursor[2 * kNH];
__device__ int g_part[2 * NCHUNK];

__device__ float g_hsum[kB * kD], g_osum[kB * kD], g_esum[kB * 32];
__device__ float g_hcnt[kB], g_ocnt[kB], g_ecnt[kB];

__device__ __forceinline__ uint32_t pack2(__nv_bfloat16 a, __nv_bfloat16 b) {
    return (uint32_t)__bfloat16_as_ushort(a) | ((uint32_t)__bfloat16_as_ushort(b) << 16);
}

// ============================================================================
// small precompute
// ============================================================================
__global__ void k_precompute(
    const float* __restrict__ Wsrc0, const float* __restrict__ asrc0,
    const float* __restrict__ Wdst0, const float* __restrict__ adst0,
    const float* __restrict__ Wedge0, const float* __restrict__ aedge0,
    const float* __restrict__ Wsrc1, const float* __restrict__ asrc1,
    const float* __restrict__ Wdst1, const float* __restrict__ adst1,
    const float* __restrict__ Wedge1, const float* __restrict__ aedge1)
{
    int rel = blockIdx.x / kL;
    int l   = blockIdx.x % kL;
    const float* Wsrc  = rel ? Wsrc1  : Wsrc0;
    const float* asrc  = rel ? asrc1  : asrc0;
    const float* Wdst  = rel ? Wdst1  : Wdst0;
    const float* adst  = rel ? adst1  : adst0;
    const float* Wedge = rel ? Wedge1 : Wedge0;
    const float* aedge = rel ? aedge1 : aedge0;

    int i = threadIdx.x;
    float s1 = 0.f, s2 = 0.f;
    const float* wsr = Wsrc + (long)l * kD * kD + (long)i * kD;
    const float* wdr = Wdst + (long)l * kD * kD + (long)i * kD;
    const float* as  = asrc + l * kD;
    const float* ad  = adst + l * kD;
    for (int j = 0; j < kD; j++) { s1 += wsr[j] * as[j]; s2 += wdr[j] * ad[j]; }
    g_vsrc[(rel * kL + l) * kD + i] = s1;
    g_vdst[(rel * kL + l) * kD + i] = s2;
    if (i < 2) {
        float c = 0.f;
        const float* we = Wedge + (long)l * 2 * kD + (long)i * kD;
        const float* ae = aedge + l * kD;
        for (int j = 0; j < kD; j++) c += we[j] * ae[j];
        g_cedge[(rel * kL + l) * 2 + i] = c;
    }
}

// ---------------- transpose + bf16 hi/lo split of Wsrc weights ----------------
__global__ void k_wprep(const float* __restrict__ W_ho, const float* __restrict__ W_oh)
{
    int rl = blockIdx.x;
    int rel = rl >> 3;
    const float* W = (rel ? W_oh : W_ho) + (long)(rl & 7) * kD * kD;
    int tile = blockIdx.y;
    int tk = (tile & 7) * 32, tn = (tile >> 3) * 32;
    __shared__ float s[32][33];
    int tx = threadIdx.x, ty = threadIdx.y;
    for (int yy = ty; yy < 32; yy += 8)
        s[yy][tx] = W[(long)(tk + yy) * kD + tn + tx];
    __syncthreads();
    __nv_bfloat16* outHi = g_wTb + (long)rl * 2 * kD * kD;
    __nv_bfloat16* outLo = outHi + kD * kD;
    for (int yy = ty; yy < 32; yy += 8) {
        float v = s[tx][yy];
        __nv_bfloat16 h = __float2bfloat16(v);
        __nv_bfloat16 l = __float2bfloat16(v - __bfloat162float(h));
        outHi[(long)(tn + yy) * kD + tk + tx] = h;
        outLo[(long)(tn + yy) * kD + tk + tx] = l;
    }
}

// ---------------- CSR build (dual-relation) ----------------
__global__ void k_hist(const int* __restrict__ d0, const int* __restrict__ d1,
                       int* __restrict__ cnt)
{
    int e = blockIdx.x * blockDim.x + threadIdx.x;
    if (e >= kE) return;
    int rel = blockIdx.y;
    const int* d = rel ? d1 : d0;
    atomicAdd(&cnt[rel * kNH + d[e]], 1);
}

__global__ void k_scan_part(const int* __restrict__ cnt, int* __restrict__ part)
{
    int rel = blockIdx.y, ch = blockIdx.x;
    const int* c = cnt + rel * kNH + ch * SCHUNK;
    int n = min(SCHUNK, kNH - ch * SCHUNK);
    int t = threadIdx.x, lane = t & 31, wid = t >> 5;
    int s = 0;
    for (int i = t; i < n; i += 256) s += c[i];
#pragma unroll
    for (int o = 16; o > 0; o >>= 1) s += __shfl_xor_sync(0xffffffffu, s, o);
    __shared__ int ws[8];
    if (lane == 0) ws[wid] = s;
    __syncthreads();
    if (t == 0) {
        int tot = 0;
        for (int k = 0; k < 8; k++) tot += ws[k];
        part[rel * NCHUNK + ch] = tot;
    }
}

__global__ void k_scan_mid(int* __restrict__ part)
{
    int rel = threadIdx.x;
    if (rel < 2) {
        int run = 0;
        for (int i = 0; i < NCHUNK; i++) {
            int v = part[rel * NCHUNK + i];
            part[rel * NCHUNK + i] = run;
            run += v;
        }
    }
}

__global__ void k_scan_apply(int* __restrict__ cnt, int* __restrict__ off,
                             const int* __restrict__ part)
{
    int rel = blockIdx.y, ch = blockIdx.x;
    int* cc = cnt + rel * kNH;
    int* oo = off + rel * (kNH + 1);
    int start = ch * SCHUNK;
    int n = min(SCHUNK, kNH - start);
    int t = threadIdx.x, lane = t & 31, wid = t >> 5;
    __shared__ int wsum[8];
    int carry = part[rel * NCHUNK + ch];
    for (int b0 = 0; b0 < n; b0 += 256) {
        int i = start + b0 + t;
        int c = (b0 + t < n) ? cc[i] : 0;
        int v = c;
#pragma unroll
        for (int o = 1; o < 32; o <<= 1) {
            int u = __shfl_up_sync(0xffffffffu, v, o);
            if (lane >= o) v += u;
        }
        if (lane == 31) wsum[wid] = v;
        __syncthreads();
        int wpre = 0, btot = 0;
#pragma unroll
        for (int k = 0; k < 8; k++) {
            int ws = wsum[k];
            if (k < wid) wpre += ws;
            btot += ws;
        }
        int excl = carry + (v - c) + wpre;
        if (b0 + t < n) { oo[i] = excl; cc[i] = excl; }
        carry += btot;
        __syncthreads();
    }
    if (t == 0 && ch == 0) oo[kNH] = kE;
}

__global__ void k_scatter(const int* __restrict__ d0, const int* __restrict__ d1,
                          int* __restrict__ cur, int* __restrict__ eid)
{
    int e = blockIdx.x * blockDim.x + threadIdx.x;
    if (e >= kE) return;
    int rel = blockIdx.y;
    const int* d = rel ? d1 : d0;
    int p = atomicAdd(&cur[rel * kNH + d[e]], 1);
    eid[rel * kE + p] = e;
}

// ---------------- fused dual matvec ----------------
__global__ void k_matvec2_dual(const float* __restrict__ xh, const float* __restrict__ xo,
                               const float* __restrict__ vh1, const float* __restrict__ vh2,
                               const float* __restrict__ vo1, const float* __restrict__ vo2,
                               float* __restrict__ aSho, float* __restrict__ aDoh,
                               float* __restrict__ aDho, float* __restrict__ aSoh)
{
    int gw = (blockIdx.x * blockDim.x + threadIdx.x) >> 5;
    int lane = threadIdx.x & 31;
    if (gw >= kNH + kNO) return;
    int rel = gw >= kNH;
    int w = rel ? gw - kNH : gw;
    const float* x  = rel ? xo  : xh;
    const float* v1 = rel ? vo1 : vh1;
    const float* v2 = rel ? vo2 : vh2;
    float* o1 = rel ? aDho : aSho;
    float* o2 = rel ? aSoh : aDoh;

    const float* xr = x + (long)w * kD;
    float s1 = 0.f, s2 = 0.f;
#pragma unroll
    for (int k = 0; k < 8; k++) {
        float xv = xr[lane + 32 * k];
        s1 += xv * v1[lane + 32 * k];
        s2 += xv * v2[lane + 32 * k];
    }
#pragma unroll
    for (int o = 16; o > 0; o >>= 1) {
        s1 += __shfl_xor_sync(0xffffffffu, s1, o);
        s2 += __shfl_xor_sync(0xffffffffu, s2, o);
    }
    if (lane == 0) { o1[w] = s1; o2[w] = s2; }
}

// ---------------- dual per-dst segment softmax + weighted gather-aggregate ----------------
__global__ void k_aggregate_dual(
    const int* __restrict__ off, const int* __restrict__ eid,
    const int* __restrict__ src0, const float* __restrict__ ea0,
    const float* __restrict__ aS0, const float* __restrict__ aD0,
    const float* __restrict__ x0, const float* __restrict__ ced0, float* __restrict__ agg0,
    const int* __restrict__ src1, const float* __restrict__ ea1,
    const float* __restrict__ aS1, const float* __restrict__ aD1,
    const float* __restrict__ x1, const float* __restrict__ ced1, float* __restrict__ agg1)
{
    int gw = (blockIdx.x * blockDim.x + threadIdx.x) >> 5;
    int lane = threadIdx.x & 31;
    if (gw >= kNO + kNH) return;
    int rel = gw >= kNO;
    int w = rel ? gw - kNO : gw;
    const int* o    = off + rel * (kNH + 1);
    const int* ei   = eid + rel * kE;
    const int* src  = rel ? src1 : src0;
    const float* ea = rel ? ea1 : ea0;
    const float* aS = rel ? aS1 : aS0;
    const float* aD = rel ? aD1 : aD0;
    const float* x  = rel ? x1 : x0;
    const float* ced = rel ? ced1 : ced0;
    float* agg = rel ? agg1 : agg0;

    int beg = o[w], end = o[w + 1];
    float c0 = ced[0], c1 = ced[1];
    float ad = aD[w];

    float m = -3.0e38f;
    for (int i = beg + lane; i < end; i += 32) {
        int e = ei[i];
        float lg = aS[src[e]] + ad + c0 * ea[2 * e] + c1 * ea[2 * e + 1];
        lg = lg > 0.f ? lg : 0.2f * lg;
        m = fmaxf(m, lg);
    }
#pragma unroll
    for (int o2 = 16; o2 > 0; o2 >>= 1) m = fmaxf(m, __shfl_xor_sync(0xffffffffu, m, o2));

    float den = 0.f;
    for (int i = beg + lane; i < end; i += 32) {
        int e = ei[i];
        float lg = aS[src[e]] + ad + c0 * ea[2 * e] + c1 * ea[2 * e + 1];
        lg = lg > 0.f ? lg : 0.2f * lg;
        den += expf(lg - m);
    }
#pragma unroll
    for (int o2 = 16; o2 > 0; o2 >>= 1) den += __shfl_xor_sync(0xffffffffu, den, o2);

    float inv = (den > 0.f) ? 1.f / den : 0.f;
    float acc[8] = {0.f, 0.f, 0.f, 0.f, 0.f, 0.f, 0.f, 0.f};
    for (int i = beg; i < end; i++) {
        int e = ei[i];
        int s = src[e];
        float lg = aS[s] + ad + c0 * ea[2 * e] + c1 * ea[2 * e + 1];
        lg = lg > 0.f ? lg : 0.2f * lg;
        float wt = expf(lg - m) * inv;
        const float* xr = x + (long)s * kD;
#pragma unroll
        for (int k = 0; k < 8; k++) acc[k] += wt * xr[lane + 32 * k];
    }
    float* ar = agg + (long)w * kD;
#pragma unroll
    for (int k = 0; k < 8; k++) ar[lane + 32 * k] = acc[k];
}

// ============================================================================
// mma.sync bf16 GEMM (3xBF16), double-buffered + register-prefetched mainloop.
// out = relu(A@W + bias) (+ prev). CTA tile 128M x 128N, 16 warps (32x32 each).
// ============================================================================
static constexpr int HSTRIDE = 40;
static constexpr int BUFH = 4 * 128 * HSTRIDE;        // halfs per stage (40960 B)
static constexpr int GEMM_SMEM = 2 * BUFH * 2;        // 81920 B

__device__ __forceinline__ void mma_bf16(float* c, const uint32_t* a, const uint32_t* b) {
    asm volatile(
        "mma.sync.aligned.m16n8k16.row.col.f32.bf16.bf16.f32 "
        "{%0,%1,%2,%3}, {%4,%5,%6,%7}, {%8,%9}, {%0,%1,%2,%3};\n"
        : "+f"(c[0]), "+f"(c[1]), "+f"(c[2]), "+f"(c[3])
        : "r"(a[0]), "r"(a[1]), "r"(a[2]), "r"(a[3]), "r"(b[0]), "r"(b[1]));
}

__global__ void __launch_bounds__(512) k_gemm_mma(
    const float* __restrict__ A0, const float* __restrict__ A1,
    const __nv_bfloat16* __restrict__ WT0, const __nv_bfloat16* __restrict__ WT1,
    const float* __restrict__ bias0, const float* __restrict__ bias1,
    const float* __restrict__ prev0, const float* __restrict__ prev1,
    float* __restrict__ out0, float* __restrict__ out1, int M)
{
    extern __shared__ __nv_bfloat16 smh[];

    const int z = blockIdx.z;
    const float* A = z ? A1 : A0;
    const __nv_bfloat16* WT = z ? WT1 : WT0;
    const float* bias = z ? bias1 : bias0;
    const float* prev = z ? prev1 : prev0;
    float* out = z ? out1 : out0;

    const int tid = threadIdx.x;
    const int w = tid >> 5, lane = tid & 31;
    const int wm = w & 3, wn = w >> 2;
    const int grp = lane >> 2, qt = lane & 3;
    const int mBase = blockIdx.y * 128;
    const int nBase = blockIdx.x * 128;

    const __nv_bfloat16* WThi = WT + (long)nBase * kD;
    const __nv_bfloat16* WTlo = WT + (long)kD * kD + (long)nBase * kD;

    // per-thread load slots: rows r0 and r0+64, columns q0*4..q0*4+3 of the 32-k chunk
    const int r0 = tid >> 3, q0 = tid & 7;
    const int gm0 = mBase + r0, gm1 = mBase + r0 + 64;

    float4 pa0, pa1;
    uint2 pbh0, pbl0, pbh1, pbl1;

    float acc[2][4][4];
#pragma unroll
    for (int i = 0; i < 2; i++)
#pragma unroll
        for (int j = 0; j < 4; j++)
#pragma unroll
            for (int q = 0; q < 4; q++) acc[i][j][q] = 0.f;

#define LOADG(c)                                                                    \
    do {                                                                            \
        pa0 = (gm0 < M) ? *(const float4*)&A[(long)gm0 * kD + (c) * 32 + q0 * 4]    \
                        : make_float4(0.f, 0.f, 0.f, 0.f);                          \
        pa1 = (gm1 < M) ? *(const float4*)&A[(long)gm1 * kD + (c) * 32 + q0 * 4]    \
                        : make_float4(0.f, 0.f, 0.f, 0.f);                          \
        pbh0 = *(const uint2*)&WThi[(long)r0 * kD + (c) * 32 + q0 * 4];             \
        pbl0 = *(const uint2*)&WTlo[(long)r0 * kD + (c) * 32 + q0 * 4];             \
        pbh1 = *(const uint2*)&WThi[(long)(r0 + 64) * kD + (c) * 32 + q0 * 4];      \
        pbl1 = *(const uint2*)&WTlo[(long)(r0 + 64) * kD + (c) * 32 + q0 * 4];      \
    } while (0)

#define CVTSTORE(buf)                                                               \
    do {                                                                            \
        __nv_bfloat16* dAhi = smh + (buf) * BUFH;                                   \
        __nv_bfloat16* dAlo = dAhi + 128 * HSTRIDE;                                 \
        __nv_bfloat16* dBhi = dAhi + 2 * 128 * HSTRIDE;                             \
        __nv_bfloat16* dBlo = dAhi + 3 * 128 * HSTRIDE;                             \
        {                                                                           \
            float4 v = pa0;                                                         \
            __nv_bfloat16 hx = __float2bfloat16(v.x), hy = __float2bfloat16(v.y);   \
            __nv_bfloat16 hz = __float2bfloat16(v.z), hw = __float2bfloat16(v.w);   \
            __nv_bfloat16 lx = __float2bfloat16(v.x - __bfloat162float(hx));        \
            __nv_bfloat16 ly = __float2bfloat16(v.y - __bfloat162float(hy));        \
            __nv_bfloat16 lz = __float2bfloat16(v.z - __bfloat162float(hz));        \
            __nv_bfloat16 lw = __float2bfloat16(v.w - __bfloat162float(hw));        \
            uint2 hv, lv;                                                           \
            hv.x = pack2(hx, hy); hv.y = pack2(hz, hw);                             \
            lv.x = pack2(lx, ly); lv.y = pack2(lz, lw);                             \
            *(uint2*)&dAhi[r0 * HSTRIDE + q0 * 4] = hv;                             \
            *(uint2*)&dAlo[r0 * HSTRIDE + q0 * 4] = lv;                             \
        }                                                                           \
        {                                                                           \
            float4 v = pa1;                                                         \
            __nv_bfloat16 hx = __float2bfloat16(v.x), hy = __float2bfloat16(v.y);   \
            __nv_bfloat16 hz = __float2bfloat16(v.z), hw = __float2bfloat16(v.w);   \
            __nv_bfloat16 lx = __float2bfloat16(v.x - __bfloat162float(hx));        \
            __nv_bfloat16 ly = __float2bfloat16(v.y - __bfloat162float(hy));        \
            __nv_bfloat16 lz = __float2bfloat16(v.z - __bfloat162float(hz));        \
            __nv_bfloat16 lw = __float2bfloat16(v.w - __bfloat162float(hw));        \
            uint2 hv, lv;                                                           \
            hv.x = pack2(hx, hy); hv.y = pack2(hz, hw);                             \
            lv.x = pack2(lx, ly); lv.y = pack2(lz, lw);                             \
            *(uint2*)&dAhi[(r0 + 64) * HSTRIDE + q0 * 4] = hv;                      \
            *(uint2*)&dAlo[(r0 + 64) * HSTRIDE + q0 * 4] = lv;                      \
        }                                                                           \
        *(uint2*)&dBhi[r0 * HSTRIDE + q0 * 4] = pbh0;                               \
        *(uint2*)&dBlo[r0 * HSTRIDE + q0 * 4] = pbl0;                               \
        *(uint2*)&dBhi[(r0 + 64) * HSTRIDE + q0 * 4] = pbh1;                        \
        *(uint2*)&dBlo[(r0 + 64) * HSTRIDE + q0 * 4] = pbl1;                        \
    } while (0)

    // prologue: stage chunk 0
    LOADG(0);
    CVTSTORE(0);
    __syncthreads();

#pragma unroll 1
    for (int c = 0; c < 8; c++) {
        const int cur = c & 1;
        if (c < 7) LOADG(c + 1);

        const __nv_bfloat16* sAhi = smh + cur * BUFH;
        const __nv_bfloat16* sAlo = sAhi + 128 * HSTRIDE;
        const __nv_bfloat16* sBhi = sAhi + 2 * 128 * HSTRIDE;
        const __nv_bfloat16* sBlo = sAhi + 3 * 128 * HSTRIDE;
#pragma unroll
        for (int ks = 0; ks < 2; ks++) {
            int kb = ks * 16;
            uint32_t ahi[2][4], alo[2][4], bhi[4][2], blo[4][2];
#pragma unroll
            for (int i = 0; i < 2; i++) {
                int ra = (wm * 32 + i * 16 + grp) * HSTRIDE + kb + qt * 2;
                ahi[i][0] = *(const uint32_t*)&sAhi[ra];
                ahi[i][1] = *(const uint32_t*)&sAhi[ra + 8 * HSTRIDE];
                ahi[i][2] = *(const uint32_t*)&sAhi[ra + 8];
                ahi[i][3] = *(const uint32_t*)&sAhi[ra + 8 * HSTRIDE + 8];
                alo[i][0] = *(const uint32_t*)&sAlo[ra];
                alo[i][1] = *(const uint32_t*)&sAlo[ra + 8 * HSTRIDE];
                alo[i][2] = *(const uint32_t*)&sAlo[ra + 8];
                alo[i][3] = *(const uint32_t*)&sAlo[ra + 8 * HSTRIDE + 8];
            }
#pragma unroll
            for (int j = 0; j < 4; j++) {
                int rb = (wn * 32 + j * 8 + grp) * HSTRIDE + kb + qt * 2;
                bhi[j][0] = *(const uint32_t*)&sBhi[rb];
                bhi[j][1] = *(const uint32_t*)&sBhi[rb + 8];
                blo[j][0] = *(const uint32_t*)&sBlo[rb];
                blo[j][1] = *(const uint32_t*)&sBlo[rb + 8];
            }
#pragma unroll
            for (int i = 0; i < 2; i++)
#pragma unroll
                for (int j = 0; j < 4; j++) {
                    mma_bf16(acc[i][j], ahi[i], bhi[j]);
                    mma_bf16(acc[i][j], ahi[i], blo[j]);
                    mma_bf16(acc[i][j], alo[i], bhi[j]);
                }
        }
        if (c < 7) CVTSTORE(cur ^ 1);
        __syncthreads();
    }
#undef LOADG
#undef CVTSTORE

    // epilogue
#pragma unroll
    for (int i = 0; i < 2; i++) {
#pragma unroll
        for (int h = 0; h < 2; h++) {
            int row = mBase + wm * 32 + i * 16 + grp + h * 8;
            if (row >= M) continue;
#pragma unroll
            for (int j = 0; j < 4; j++) {
                int col = nBase + wn * 32 + j * 8 + qt * 2;
                float v0 = acc[i][j][h * 2 + 0] + bias[col];
                float v1 = acc[i][j][h * 2 + 1] + bias[col + 1];
                v0 = fmaxf(v0, 0.f);
                v1 = fmaxf(v1, 0.f);
                if (prev) {
                    float2 pv = *(const float2*)&prev[(long)row * kD + col];
                    v0 += pv.x; v1 += pv.y;
                }
                float2 o; o.x = v0; o.y = v1;
                *(float2*)&out[(long)row * kD + col] = o;
            }
        }
    }
}

// ---------------- pooling ----------------
__global__ void k_pool_nodes(const float* __restrict__ x, const int* __restrict__ batch,
                             float* __restrict__ sum, float* __restrict__ cnt, int N)
{
    long idx = (long)blockIdx.x * blockDim.x + threadIdx.x;
    if (idx >= (long)N * kD) return;
    int n = (int)(idx >> 8);
    int d = (int)(idx & 255);
    int b = batch[n];
    atomicAdd(&sum[b * kD + d], x[idx]);
    if (d == 0) atomicAdd(&cnt[b], 1.f);
}

// smem-accumulated edge pooling: 512 bins x 32 features + 512 counts per block
static constexpr int PE_SMEM = (kB * 32 + kB) * 4;  // 66560 B
__global__ void k_pool_edges(const float* __restrict__ ea, const int* __restrict__ src,
                             const int* __restrict__ hbatch,
                             const float* __restrict__ Wm, const float* __restrict__ bm,
                             float* __restrict__ esum, float* __restrict__ ecnt)
{
    extern __shared__ float sm[];
    float* ss = sm;            // kB*32
    float* sc = sm + kB * 32;  // kB
    for (int i = threadIdx.x; i < kB * 32 + kB; i += blockDim.x) sm[i] = 0.f;
    __syncthreads();
    for (int e = blockIdx.x * blockDim.x + threadIdx.x; e < kE; e += gridDim.x * blockDim.x) {
        float e0 = ea[2 * e], e1 = ea[2 * e + 1];
        int b = hbatch[src[e]];
        atomicAdd(&sc[b], 1.f);
#pragma unroll
        for (int j = 0; j < 32; j++) {
            float v = fmaxf(e0 * Wm[j] + e1 * Wm[32 + j] + bm[j], 0.f);
            atomicAdd(&ss[b * 32 + j], v);
        }
    }
    __syncthreads();
    for (int i = threadIdx.x; i < kB * 32; i += blockDim.x)
        if (ss[i] != 0.f) atomicAdd(&esum[i], ss[i]);
    for (int i = threadIdx.x; i < kB; i += blockDim.x)
        if (sc[i] != 0.f) atomicAdd(&ecnt[i], sc[i]);
}

// ---------------- final: graph emb -> 2 softmax heads ----------------
__global__ void k_final(const float* __restrict__ hsum, const float* __restrict__ hcnt,
                        const float* __restrict__ osum, const float* __restrict__ ocnt,
                        const float* __restrict__ esum, const float* __restrict__ ecnt,
                        const float* __restrict__ Wp1, const float* __restrict__ bp1,
                        const float* __restrict__ Wp2, const float* __restrict__ bp2,
                        float* __restrict__ out)
{
    __shared__ float emb[2 * kD + 32];
    __shared__ float red[128];
    int b = blockIdx.x, t = threadIdx.x;
    float hc = fmaxf(hcnt[b], 1.f), oc = fmaxf(ocnt[b], 1.f), ec = fmaxf(ecnt[b], 1.f);
    for (int k = t; k < kD; k += 128) {
        emb[k]      = hsum[b * kD + k] / hc;
        emb[kD + k] = osum[b * kD + k] / oc;
    }
    for (int k = t; k < 32; k += 128) emb[2 * kD + k] = esum[b * 32 + k] / ec;
    __syncthreads();

    for (int head = 0; head < 2; head++) {
        const float* W  = head ? Wp2 : Wp1;
        const float* bb = head ? bp2 : bp1;
        float v = -3.0e38f;
        if (t < kC) {
            v = bb[t];
            for (int k = 0; k < 2 * kD + 32; k++) v += emb[k] * W[k * kC + t];
        }
        red[t] = v;
        __syncthreads();
        for (int s = 64; s > 0; s >>= 1) {
            if (t < s) red[t] = fmaxf(red[t], red[t + s]);
            __syncthreads();
        }
        float mx = red[0];
        __syncthreads();
        float ex = (t < kC) ? expf(v - mx) : 0.f;
        red[t] = ex;
        __syncthreads();
        for (int s = 64; s > 0; s >>= 1) {
            if (t < s) red[t] += red[t + s];
            __syncthreads();
        }
        float sm = red[0];
        __syncthreads();
        if (t < kC) out[(b * 2 + head) * kC + t] = ex / sm;
    }
}

// ---------------- launch ----------------
extern "C" void kernel_launch(void* const* d_in, const int* in_sizes, int n_in,
                              void* d_out, int out_size)
{
    const float* x_human = (const float*)d_in[0];
    const float* x_object = (const float*)d_in[1];
    const int* ei_ho = (const int*)d_in[2];
    const int* ei_oh = (const int*)d_in[3];
    const float* ea_ho = (const float*)d_in[4];
    const float* ea_oh = (const float*)d_in[5];
    const int* hbatch = (const int*)d_in[6];
    const int* obatch = (const int*)d_in[7];
    const float* Wsrc_ho = (const float*)d_in[8];
    const float* Wdst_ho = (const float*)d_in[9];
    const float* asrc_ho = (const float*)d_in[10];
    const float* adst_ho = (const float*)d_in[11];
    const float* Wedge_ho = (const float*)d_in[12];
    const float* aedge_ho = (const float*)d_in[13];
    const float* bias_ho = (const float*)d_in[14];
    const float* Wsrc_oh = (const float*)d_in[15];
    const float* Wdst_oh = (const float*)d_in[16];
    const float* asrc_oh = (const float*)d_in[17];
    const float* adst_oh = (const float*)d_in[18];
    const float* Wedge_oh = (const float*)d_in[19];
    const float* aedge_oh = (const float*)d_in[20];
    const float* bias_oh = (const float*)d_in[21];
    const float* W_emlp = (const float*)d_in[22];
    const float* b_emlp = (const float*)d_in[23];
    const float* W_p1 = (const float*)d_in[24];
    const float* b_p1 = (const float*)d_in[25];
    const float* W_p2 = (const float*)d_in[26];
    const float* b_p2 = (const float*)d_in[27];

    float *h0, *h1, *o0, *o1, *agg0, *agg1;
    float *aSho, *aDoh, *aDho, *aSoh, *vsrc, *vdst, *ced;
    float *hsum, *osum, *esum, *hcnt, *ocnt, *ecnt;
    __nv_bfloat16* wTb;
    int *off, *eid, *cur, *part;
    cudaGetSymbolAddress((void**)&h0, g_h0);
    cudaGetSymbolAddress((void**)&h1, g_h1);
    cudaGetSymbolAddress((void**)&o0, g_o0);
    cudaGetSymbolAddress((void**)&o1, g_o1);
    cudaGetSymbolAddress((void**)&agg0, g_agg0);
    cudaGetSymbolAddress((void**)&agg1, g_agg1);
    cudaGetSymbolAddress((void**)&aSho, g_aSho);
    cudaGetSymbolAddress((void**)&aDoh, g_aDoh);
    cudaGetSymbolAddress((void**)&aDho, g_aDho);
    cudaGetSymbolAddress((void**)&aSoh, g_aSoh);
    cudaGetSymbolAddress((void**)&vsrc, g_vsrc);
    cudaGetSymbolAddress((void**)&vdst, g_vdst);
    cudaGetSymbolAddress((void**)&ced, g_cedge);
    cudaGetSymbolAddress((void**)&wTb, g_wTb);
    cudaGetSymbolAddress((void**)&off, g_off);
    cudaGetSymbolAddress((void**)&eid, g_eid);
    cudaGetSymbolAddress((void**)&cur, g_cursor);
    cudaGetSymbolAddress((void**)&part, g_part);
    cudaGetSymbolAddress((void**)&hsum, g_hsum);
    cudaGetSymbolAddress((void**)&osum, g_osum);
    cudaGetSymbolAddress((void**)&esum, g_esum);
    cudaGetSymbolAddress((void**)&hcnt, g_hcnt);
    cudaGetSymbolAddress((void**)&ocnt, g_ocnt);
    cudaGetSymbolAddress((void**)&ecnt, g_ecnt);

    cudaFuncSetAttribute(k_gemm_mma, cudaFuncAttributeMaxDynamicSharedMemorySize, GEMM_SMEM);
    cudaFuncSetAttribute(k_pool_edges, cudaFuncAttributeMaxDynamicSharedMemorySize, PE_SMEM);

    const int EB = (kE + 255) / 256;
    const dim3 GEMM_GRID(2, (kNH + 127) / 128, 2);

    // ---- CSR build for both relations ----
    cudaMemsetAsync(cur, 0, sizeof(int) * 2 * kNH);
    k_hist<<<dim3(EB, 2), 256>>>(ei_ho + kE, ei_oh + kE, cur);
    k_scan_part<<<dim3(NCHUNK, 2), 256>>>(cur, part);
    k_scan_mid<<<1, 32>>>(part);
    k_scan_apply<<<dim3(NCHUNK, 2), 256>>>(cur, off, part);
    k_scatter<<<dim3(EB, 2), 256>>>(ei_ho + kE, ei_oh + kE, cur, eid);

    // ---- per-layer precompute ----
    k_precompute<<<2 * kL, 256>>>(Wsrc_ho, asrc_ho, Wdst_ho, adst_ho, Wedge_ho, aedge_ho,
                                  Wsrc_oh, asrc_oh, Wdst_oh, adst_oh, Wedge_oh, aedge_oh);
    k_wprep<<<dim3(16, 64), dim3(32, 8)>>>(Wsrc_ho, Wsrc_oh);

    // ---- 8 layers ----
    const float* cur_h = x_human;
    const float* cur_o = x_object;
    for (int l = 0; l < kL; l++) {
        float* nh = (l & 1) ? h1 : h0;
        float* no = (l & 1) ? o1 : o0;

        k_matvec2_dual<<<(kNH + kNO) / 8, 256>>>(
            cur_h, cur_o,
            vsrc + (0 * kL + l) * kD, vdst + (1 * kL + l) * kD,
            vdst + (0 * kL + l) * kD, vsrc + (1 * kL + l) * kD,
            aSho, aDoh, aDho, aSoh);

        k_aggregate_dual<<<(kNO + kNH) / 8, 256>>>(
            off, eid,
            ei_ho, ea_ho, aSho, aDho, cur_h, ced + (0 * kL + l) * 2, agg0,
            ei_oh, ea_oh, aSoh, aDoh, cur_o, ced + (1 * kL + l) * 2, agg1);

        k_gemm_mma<<<GEMM_GRID, 512, GEMM_SMEM>>>(
            agg0, agg1,
            wTb + (long)(0 * kL + l) * 2 * kD * kD, wTb + (long)(1 * kL + l) * 2 * kD * kD,
            bias_ho + l * kD, bias_oh + l * kD,
            l ? cur_o : nullptr, l ? cur_h : nullptr,
            no, nh, kNO);

        cur_h = nh;
        cur_o = no;
    }

    // ---- pooling ----
    cudaMemsetAsync(hsum, 0, sizeof(float) * kB * kD);
    cudaMemsetAsync(osum, 0, sizeof(float) * kB * kD);
    cudaMemsetAsync(esum, 0, sizeof(float) * kB * 32);
    cudaMemsetAsync(hcnt, 0, sizeof(float) * kB);
    cudaMemsetAsync(ocnt, 0, sizeof(float) * kB);
    cudaMemsetAsync(ecnt, 0, sizeof(float) * kB);
    k_pool_nodes<<<kNH, 256>>>(cur_h, hbatch, hsum, hcnt, kNH);
    k_pool_nodes<<<kNO, 256>>>(cur_o, obatch, osum, ocnt, kNO);
    k_pool_edges<<<132, 256, PE_SMEM>>>(ea_ho, ei_ho, hbatch, W_emlp, b_emlp, esum, ecnt);

    // ---- classifier heads ----
    k_final<<<kB, 128>>>(hsum, hcnt, osum, ocnt, esum, ecnt,
                         W_p1, b_p1, W_p2, b_p2, (float*)d_out);
}

// round 11
// speedup vs baseline: 1.6506x; 1.0729x over previous
#include <cuda_runtime.h>
#include <cuda_bf16.h>
#include <cstdint>

static constexpr int kNH = 50000;
static constexpr int kNO = 50000;
static constexpr int kE  = 500000;
static constexpr int kD  = 256;
static constexpr int kL  = 8;
static constexpr int kB  = 512;
static constexpr int kC  = 117;

// ---------------- device scratch (static, no runtime alloc) ----------------
__device__ float g_h0[kNH * kD];
__device__ float g_h1[kNH * kD];
__device__ float g_o0[kNO * kD];
__device__ float g_o1[kNO * kD];
__device__ float g_agg0[kNO * kD];
__device__ float g_agg1[kNH * kD];

__device__ float g_aSho[kNH], g_aDoh[kNH], g_aDho[kNO], g_aSoh[kNO];

__device__ float g_vsrc[2 * kL * kD];
__device__ float g_vdst[2 * kL * kD];
__device__ float g_cedge[2 * kL * 2];

// W^T as bf16 hi/lo: [rel*8+layer][hi/lo][n=256][k=256]
__device__ __nv_bfloat16 g_wTb[2 * kL * 2 * kD * kD];

static constexpr int SCHUNK = 4096;
static constexpr int NCHUNK = (kNH + SCHUNK - 1) / SCHUNK;  // 13

__device__ int g_off[2 * (kNH + 1)];
__device__ int g_eid[2 * kE];
__device__ int g_cursor[2 * kNH];
__device__ int g_part[2 * NCHUNK];

// CSR-ordered edge data (built once): source node id + edge attrs
__device__ int    g_srcs[2 * kE];
__device__ float2 g_ea2[2 * kE];

__device__ float g_hsum[kB * kD], g_osum[kB * kD], g_esum[kB * 32];
__device__ float g_hcnt[kB], g_ocnt[kB], g_ecnt[kB];

__device__ __forceinline__ uint32_t pack2(__nv_bfloat16 a, __nv_bfloat16 b) {
    return (uint32_t)__bfloat16_as_ushort(a) | ((uint32_t)__bfloat16_as_ushort(b) << 16);
}

// ============================================================================
// small precompute
// ============================================================================
__global__ void k_precompute(
    const float* __restrict__ Wsrc0, const float* __restrict__ asrc0,
    const float* __restrict__ Wdst0, const float* __restrict__ adst0,
    const float* __restrict__ Wedge0, const float* __restrict__ aedge0,
    const float* __restrict__ Wsrc1, const float* __restrict__ asrc1,
    const float* __restrict__ Wdst1, const float* __restrict__ adst1,
    const float* __restrict__ Wedge1, const float* __restrict__ aedge1)
{
    int rel = blockIdx.x / kL;
    int l   = blockIdx.x % kL;
    const float* Wsrc  = rel ? Wsrc1  : Wsrc0;
    const float* asrc  = rel ? asrc1  : asrc0;
    const float* Wdst  = rel ? Wdst1  : Wdst0;
    const float* adst  = rel ? adst1  : adst0;
    const float* Wedge = rel ? Wedge1 : Wedge0;
    const float* aedge = rel ? aedge1 : aedge0;

    int i = threadIdx.x;
    float s1 = 0.f, s2 = 0.f;
    const float* wsr = Wsrc + (long)l * kD * kD + (long)i * kD;
    const float* wdr = Wdst + (long)l * kD * kD + (long)i * kD;
    const float* as  = asrc + l * kD;
    const float* ad  = adst + l * kD;
    for (int j = 0; j < kD; j++) { s1 += wsr[j] * as[j]; s2 += wdr[j] * ad[j]; }
    g_vsrc[(rel * kL + l) * kD + i] = s1;
    g_vdst[(rel * kL + l) * kD + i] = s2;
    if (i < 2) {
        float c = 0.f;
        const float* we = Wedge + (long)l * 2 * kD + (long)i * kD;
        const float* ae = aedge + l * kD;
        for (int j = 0; j < kD; j++) c += we[j] * ae[j];
        g_cedge[(rel * kL + l) * 2 + i] = c;
    }
}

// ---------------- transpose + bf16 hi/lo split of Wsrc weights ----------------
__global__ void k_wprep(const float* __restrict__ W_ho, const float* __restrict__ W_oh)
{
    int rl = blockIdx.x;
    int rel = rl >> 3;
    const float* W = (rel ? W_oh : W_ho) + (long)(rl & 7) * kD * kD;
    int tile = blockIdx.y;
    int tk = (tile & 7) * 32, tn = (tile >> 3) * 32;
    __shared__ float s[32][33];
    int tx = threadIdx.x, ty = threadIdx.y;
    for (int yy = ty; yy < 32; yy += 8)
        s[yy][tx] = W[(long)(tk + yy) * kD + tn + tx];
    __syncthreads();
    __nv_bfloat16* outHi = g_wTb + (long)rl * 2 * kD * kD;
    __nv_bfloat16* outLo = outHi + kD * kD;
    for (int yy = ty; yy < 32; yy += 8) {
        float v = s[tx][yy];
        __nv_bfloat16 h = __float2bfloat16(v);
        __nv_bfloat16 l = __float2bfloat16(v - __bfloat162float(h));
        outHi[(long)(tn + yy) * kD + tk + tx] = h;
        outLo[(long)(tn + yy) * kD + tk + tx] = l;
    }
}

// ---------------- CSR build (dual-relation) ----------------
__global__ void k_hist(const int* __restrict__ d0, const int* __restrict__ d1,
                       int* __restrict__ cnt)
{
    int e = blockIdx.x * blockDim.x + threadIdx.x;
    if (e >= kE) return;
    int rel = blockIdx.y;
    const int* d = rel ? d1 : d0;
    atomicAdd(&cnt[rel * kNH + d[e]], 1);
}

__global__ void k_scan_part(const int* __restrict__ cnt, int* __restrict__ part)
{
    int rel = blockIdx.y, ch = blockIdx.x;
    const int* c = cnt + rel * kNH + ch * SCHUNK;
    int n = min(SCHUNK, kNH - ch * SCHUNK);
    int t = threadIdx.x, lane = t & 31, wid = t >> 5;
    int s = 0;
    for (int i = t; i < n; i += 256) s += c[i];
#pragma unroll
    for (int o = 16; o > 0; o >>= 1) s += __shfl_xor_sync(0xffffffffu, s, o);
    __shared__ int ws[8];
    if (lane == 0) ws[wid] = s;
    __syncthreads();
    if (t == 0) {
        int tot = 0;
        for (int k = 0; k < 8; k++) tot += ws[k];
        part[rel * NCHUNK + ch] = tot;
    }
}

// merged mid-scan + apply: each block sums its chunk-prefix from raw totals
__global__ void k_scan_apply(int* __restrict__ cnt, int* __restrict__ off,
                             const int* __restrict__ part)
{
    int rel = blockIdx.y, ch = blockIdx.x;
    int* cc = cnt + rel * kNH;
    int* oo = off + rel * (kNH + 1);
    int start = ch * SCHUNK;
    int n = min(SCHUNK, kNH - start);
    int t = threadIdx.x, lane = t & 31, wid = t >> 5;
    __shared__ int wsum[8];
    int carry = 0;
    for (int k = 0; k < ch; k++) carry += part[rel * NCHUNK + k];
    for (int b0 = 0; b0 < n; b0 += 256) {
        int i = start + b0 + t;
        int c = (b0 + t < n) ? cc[i] : 0;
        int v = c;
#pragma unroll
        for (int o = 1; o < 32; o <<= 1) {
            int u = __shfl_up_sync(0xffffffffu, v, o);
            if (lane >= o) v += u;
        }
        if (lane == 31) wsum[wid] = v;
        __syncthreads();
        int wpre = 0, btot = 0;
#pragma unroll
        for (int k = 0; k < 8; k++) {
            int ws = wsum[k];
            if (k < wid) wpre += ws;
            btot += ws;
        }
        int excl = carry + (v - c) + wpre;
        if (b0 + t < n) { oo[i] = excl; cc[i] = excl; }
        carry += btot;
        __syncthreads();
    }
    if (t == 0 && ch == 0) oo[kNH] = kE;
}

__global__ void k_scatter(const int* __restrict__ d0, const int* __restrict__ d1,
                          int* __restrict__ cur, int* __restrict__ eid)
{
    int e = blockIdx.x * blockDim.x + threadIdx.x;
    if (e >= kE) return;
    int rel = blockIdx.y;
    const int* d = rel ? d1 : d0;
    int p = atomicAdd(&cur[rel * kNH + d[e]], 1);
    eid[rel * kE + p] = e;
}

// ---------------- one-time permutation of edge data into CSR order ----------------
__global__ void k_edgeprep(const int* __restrict__ eid,
                           const int* __restrict__ s0, const int* __restrict__ s1,
                           const float* __restrict__ ea0, const float* __restrict__ ea1,
                           int* __restrict__ srcs, float2* __restrict__ ea2)
{
    int p = blockIdx.x * blockDim.x + threadIdx.x;
    if (p >= kE) return;
    int rel = blockIdx.y;
    const int* s = rel ? s1 : s0;
    const float* ea = rel ? ea1 : ea0;
    int e = eid[rel * kE + p];
    srcs[rel * kE + p] = s[e];
    ea2[rel * kE + p] = make_float2(ea[2 * e], ea[2 * e + 1]);
}

// ---------------- fused dual matvec ----------------
__global__ void k_matvec2_dual(const float* __restrict__ xh, const float* __restrict__ xo,
                               const float* __restrict__ vh1, const float* __restrict__ vh2,
                               const float* __restrict__ vo1, const float* __restrict__ vo2,
                               float* __restrict__ aSho, float* __restrict__ aDoh,
                               float* __restrict__ aDho, float* __restrict__ aSoh)
{
    int gw = (blockIdx.x * blockDim.x + threadIdx.x) >> 5;
    int lane = threadIdx.x & 31;
    if (gw >= kNH + kNO) return;
    int rel = gw >= kNH;
    int w = rel ? gw - kNH : gw;
    const float* x  = rel ? xo  : xh;
    const float* v1 = rel ? vo1 : vh1;
    const float* v2 = rel ? vo2 : vh2;
    float* o1 = rel ? aDho : aSho;
    float* o2 = rel ? aSoh : aDoh;

    const float* xr = x + (long)w * kD;
    float s1 = 0.f, s2 = 0.f;
#pragma unroll
    for (int k = 0; k < 8; k++) {
        float xv = xr[lane + 32 * k];
        s1 += xv * v1[lane + 32 * k];
        s2 += xv * v2[lane + 32 * k];
    }
#pragma unroll
    for (int o = 16; o > 0; o >>= 1) {
        s1 += __shfl_xor_sync(0xffffffffu, s1, o);
        s2 += __shfl_xor_sync(0xffffffffu, s2, o);
    }
    if (lane == 0) { o1[w] = s1; o2[w] = s2; }
}

// ---------------- dual per-dst segment softmax + weighted gather-aggregate ----------------
// CSR-ordered srcs/ea2 (sequential), register-cached logits, shfl-broadcast gather.
__global__ void k_aggregate_dual(
    const int* __restrict__ off, const int* __restrict__ srcs,
    const float2* __restrict__ ea2,
    const float* __restrict__ aS0, const float* __restrict__ aD0,
    const float* __restrict__ x0, const float* __restrict__ ced0, float* __restrict__ agg0,
    const float* __restrict__ aS1, const float* __restrict__ aD1,
    const float* __restrict__ x1, const float* __restrict__ ced1, float* __restrict__ agg1)
{
    int gw = (blockIdx.x * blockDim.x + threadIdx.x) >> 5;
    int lane = threadIdx.x & 31;
    if (gw >= kNO + kNH) return;
    int rel = gw >= kNO;
    int w = rel ? gw - kNO : gw;
    const int* o     = off + rel * (kNH + 1);
    const int* sc    = srcs + rel * kE;
    const float2* e2 = ea2 + rel * kE;
    const float* aS  = rel ? aS1 : aS0;
    const float* aD  = rel ? aD1 : aD0;
    const float* x   = rel ? x1 : x0;
    const float* ced = rel ? ced1 : ced0;
    float* agg = rel ? agg1 : agg0;

    int beg = o[w], end = o[w + 1];
    int deg = end - beg;
    float c0 = ced[0], c1 = ced[1];
    float ad = aD[w];

    float4 acc0 = make_float4(0.f, 0.f, 0.f, 0.f);
    float4 acc1 = make_float4(0.f, 0.f, 0.f, 0.f);

    if (deg <= 128) {
        int sid[4];
        float ex[4];
        float m = -3.0e38f;
#pragma unroll
        for (int s = 0; s < 4; s++) {
            int i = beg + lane + 32 * s;
            bool ok = i < end;
            sid[s] = ok ? sc[i] : 0;
            float lg = -3.0e38f;
            if (ok) {
                float2 e = e2[i];
                lg = aS[sid[s]] + ad + c0 * e.x + c1 * e.y;
                lg = lg > 0.f ? lg : 0.2f * lg;
            }
            ex[s] = lg;
            m = fmaxf(m, lg);
        }
#pragma unroll
        for (int o2 = 16; o2 > 0; o2 >>= 1) m = fmaxf(m, __shfl_xor_sync(0xffffffffu, m, o2));

        float den = 0.f;
#pragma unroll
        for (int s = 0; s < 4; s++) {
            float e_ = (beg + lane + 32 * s < end) ? expf(ex[s] - m) : 0.f;
            ex[s] = e_;
            den += e_;
        }
#pragma unroll
        for (int o2 = 16; o2 > 0; o2 >>= 1) den += __shfl_xor_sync(0xffffffffu, den, o2);
        float inv = (den > 0.f) ? 1.f / den : 0.f;

#pragma unroll
        for (int s = 0; s < 4; s++) {
            int base = beg + 32 * s;
            int cnt = min(32, end - base);
            if (cnt <= 0) break;
            float wts = ex[s] * inv;
            for (int t = 0; t < cnt; t++) {
                float wt = __shfl_sync(0xffffffffu, wts, t);
                int sb   = __shfl_sync(0xffffffffu, sid[s], t);
                const float4* xr = (const float4*)(x + (long)sb * kD);
                float4 xa = xr[lane];
                float4 xb = xr[lane + 32];
                acc0.x += wt * xa.x; acc0.y += wt * xa.y;
                acc0.z += wt * xa.z; acc0.w += wt * xa.w;
                acc1.x += wt * xb.x; acc1.y += wt * xb.y;
                acc1.z += wt * xb.z; acc1.w += wt * xb.w;
            }
        }
    } else {
        // fallback for very high degree (rare): 3-pass recompute
        float m = -3.0e38f;
        for (int i = beg + lane; i < end; i += 32) {
            float2 e = e2[i];
            float lg = aS[sc[i]] + ad + c0 * e.x + c1 * e.y;
            lg = lg > 0.f ? lg : 0.2f * lg;
            m = fmaxf(m, lg);
        }
#pragma unroll
        for (int o2 = 16; o2 > 0; o2 >>= 1) m = fmaxf(m, __shfl_xor_sync(0xffffffffu, m, o2));
        float den = 0.f;
        for (int i = beg + lane; i < end; i += 32) {
            float2 e = e2[i];
            float lg = aS[sc[i]] + ad + c0 * e.x + c1 * e.y;
            lg = lg > 0.f ? lg : 0.2f * lg;
            den += expf(lg - m);
        }
#pragma unroll
        for (int o2 = 16; o2 > 0; o2 >>= 1) den += __shfl_xor_sync(0xffffffffu, den, o2);
        float inv = (den > 0.f) ? 1.f / den : 0.f;
        for (int i = beg; i < end; i++) {
            float2 e = e2[i];
            int sb = sc[i];
            float lg = aS[sb] + ad + c0 * e.x + c1 * e.y;
            lg = lg > 0.f ? lg : 0.2f * lg;
            float wt = expf(lg - m) * inv;
            const float4* xr = (const float4*)(x + (long)sb * kD);
            float4 xa = xr[lane];
            float4 xb = xr[lane + 32];
            acc0.x += wt * xa.x; acc0.y += wt * xa.y;
            acc0.z += wt * xa.z; acc0.w += wt * xa.w;
            acc1.x += wt * xb.x; acc1.y += wt * xb.y;
            acc1.z += wt * xb.z; acc1.w += wt * xb.w;
        }
    }

    float4* ar = (float4*)(agg + (long)w * kD);
    ar[lane] = acc0;
    ar[lane + 32] = acc1;
}

// ============================================================================
// mma.sync bf16 GEMM (3xBF16), double-buffered + register-prefetched (unchanged)
// ============================================================================
static constexpr int HSTRIDE = 40;
static constexpr int BUFH = 4 * 128 * HSTRIDE;
static constexpr int GEMM_SMEM = 2 * BUFH * 2;

__device__ __forceinline__ void mma_bf16(float* c, const uint32_t* a, const uint32_t* b) {
    asm volatile(
        "mma.sync.aligned.m16n8k16.row.col.f32.bf16.bf16.f32 "
        "{%0,%1,%2,%3}, {%4,%5,%6,%7}, {%8,%9}, {%0,%1,%2,%3};\n"
        : "+f"(c[0]), "+f"(c[1]), "+f"(c[2]), "+f"(c[3])
        : "r"(a[0]), "r"(a[1]), "r"(a[2]), "r"(a[3]), "r"(b[0]), "r"(b[1]));
}

__global__ void __launch_bounds__(512) k_gemm_mma(
    const float* __restrict__ A0, const float* __restrict__ A1,
    const __nv_bfloat16* __restrict__ WT0, const __nv_bfloat16* __restrict__ WT1,
    const float* __restrict__ bias0, const float* __restrict__ bias1,
    const float* __restrict__ prev0, const float* __restrict__ prev1,
    float* __restrict__ out0, float* __restrict__ out1, int M)
{
    extern __shared__ __nv_bfloat16 smh[];

    const int z = blockIdx.z;
    const float* A = z ? A1 : A0;
    const __nv_bfloat16* WT = z ? WT1 : WT0;
    const float* bias = z ? bias1 : bias0;
    const float* prev = z ? prev1 : prev0;
    float* out = z ? out1 : out0;

    const int tid = threadIdx.x;
    const int w = tid >> 5, lane = tid & 31;
    const int wm = w & 3, wn = w >> 2;
    const int grp = lane >> 2, qt = lane & 3;
    const int mBase = blockIdx.y * 128;
    const int nBase = blockIdx.x * 128;

    const __nv_bfloat16* WThi = WT + (long)nBase * kD;
    const __nv_bfloat16* WTlo = WT + (long)kD * kD + (long)nBase * kD;

    const int r0 = tid >> 3, q0 = tid & 7;
    const int gm0 = mBase + r0, gm1 = mBase + r0 + 64;

    float4 pa0, pa1;
    uint2 pbh0, pbl0, pbh1, pbl1;

    float acc[2][4][4];
#pragma unroll
    for (int i = 0; i < 2; i++)
#pragma unroll
        for (int j = 0; j < 4; j++)
#pragma unroll
            for (int q = 0; q < 4; q++) acc[i][j][q] = 0.f;

#define LOADG(c)                                                                    \
    do {                                                                            \
        pa0 = (gm0 < M) ? *(const float4*)&A[(long)gm0 * kD + (c) * 32 + q0 * 4]    \
                        : make_float4(0.f, 0.f, 0.f, 0.f);                          \
        pa1 = (gm1 < M) ? *(const float4*)&A[(long)gm1 * kD + (c) * 32 + q0 * 4]    \
                        : make_float4(0.f, 0.f, 0.f, 0.f);                          \
        pbh0 = *(const uint2*)&WThi[(long)r0 * kD + (c) * 32 + q0 * 4];             \
        pbl0 = *(const uint2*)&WTlo[(long)r0 * kD + (c) * 32 + q0 * 4];             \
        pbh1 = *(const uint2*)&WThi[(long)(r0 + 64) * kD + (c) * 32 + q0 * 4];      \
        pbl1 = *(const uint2*)&WTlo[(long)(r0 + 64) * kD + (c) * 32 + q0 * 4];      \
    } while (0)

#define CVTSTORE(buf)                                                               \
    do {                                                                            \
        __nv_bfloat16* dAhi = smh + (buf) * BUFH;                                   \
        __nv_bfloat16* dAlo = dAhi + 128 * HSTRIDE;                                 \
        __nv_bfloat16* dBhi = dAhi + 2 * 128 * HSTRIDE;                             \
        __nv_bfloat16* dBlo = dAhi + 3 * 128 * HSTRIDE;                             \
        {                                                                           \
            float4 v = pa0;                                                         \
            __nv_bfloat16 hx = __float2bfloat16(v.x), hy = __float2bfloat16(v.y);   \
            __nv_bfloat16 hz = __float2bfloat16(v.z), hw = __float2bfloat16(v.w);   \
            __nv_bfloat16 lx = __float2bfloat16(v.x - __bfloat162float(hx));        \
            __nv_bfloat16 ly = __float2bfloat16(v.y - __bfloat162float(hy));        \
            __nv_bfloat16 lz = __float2bfloat16(v.z - __bfloat162float(hz));        \
            __nv_bfloat16 lw = __float2bfloat16(v.w - __bfloat162float(hw));        \
            uint2 hv, lv;                                                           \
            hv.x = pack2(hx, hy); hv.y = pack2(hz, hw);                             \
            lv.x = pack2(lx, ly); lv.y = pack2(lz, lw);                             \
            *(uint2*)&dAhi[r0 * HSTRIDE + q0 * 4] = hv;                             \
            *(uint2*)&dAlo[r0 * HSTRIDE + q0 * 4] = lv;                             \
        }                                                                           \
        {                                                                           \
            float4 v = pa1;                                                         \
            __nv_bfloat16 hx = __float2bfloat16(v.x), hy = __float2bfloat16(v.y);   \
            __nv_bfloat16 hz = __float2bfloat16(v.z), hw = __float2bfloat16(v.w);   \
            __nv_bfloat16 lx = __float2bfloat16(v.x - __bfloat162float(hx));        \
            __nv_bfloat16 ly = __float2bfloat16(v.y - __bfloat162float(hy));        \
            __nv_bfloat16 lz = __float2bfloat16(v.z - __bfloat162float(hz));        \
            __nv_bfloat16 lw = __float2bfloat16(v.w - __bfloat162float(hw));        \
            uint2 hv, lv;                                                           \
            hv.x = pack2(hx, hy); hv.y = pack2(hz, hw);                             \
            lv.x = pack2(lx, ly); lv.y = pack2(lz, lw);                             \
            *(uint2*)&dAhi[(r0 + 64) * HSTRIDE + q0 * 4] = hv;                      \
            *(uint2*)&dAlo[(r0 + 64) * HSTRIDE + q0 * 4] = lv;                      \
        }                                                                           \
        *(uint2*)&dBhi[r0 * HSTRIDE + q0 * 4] = pbh0;                               \
        *(uint2*)&dBlo[r0 * HSTRIDE + q0 * 4] = pbl0;                               \
        *(uint2*)&dBhi[(r0 + 64) * HSTRIDE + q0 * 4] = pbh1;                        \
        *(uint2*)&dBlo[(r0 + 64) * HSTRIDE + q0 * 4] = pbl1;                        \
    } while (0)

    LOADG(0);
    CVTSTORE(0);
    __syncthreads();

#pragma unroll 1
    for (int c = 0; c < 8; c++) {
        const int cur = c & 1;
        if (c < 7) LOADG(c + 1);

        const __nv_bfloat16* sAhi = smh + cur * BUFH;
        const __nv_bfloat16* sAlo = sAhi + 128 * HSTRIDE;
        const __nv_bfloat16* sBhi = sAhi + 2 * 128 * HSTRIDE;
        const __nv_bfloat16* sBlo = sAhi + 3 * 128 * HSTRIDE;
#pragma unroll
        for (int ks = 0; ks < 2; ks++) {
            int kb = ks * 16;
            uint32_t ahi[2][4], alo[2][4], bhi[4][2], blo[4][2];
#pragma unroll
            for (int i = 0; i < 2; i++) {
                int ra = (wm * 32 + i * 16 + grp) * HSTRIDE + kb + qt * 2;
                ahi[i][0] = *(const uint32_t*)&sAhi[ra];
                ahi[i][1] = *(const uint32_t*)&sAhi[ra + 8 * HSTRIDE];
                ahi[i][2] = *(const uint32_t*)&sAhi[ra + 8];
                ahi[i][3] = *(const uint32_t*)&sAhi[ra + 8 * HSTRIDE + 8];
                alo[i][0] = *(const uint32_t*)&sAlo[ra];
                alo[i][1] = *(const uint32_t*)&sAlo[ra + 8 * HSTRIDE];
                alo[i][2] = *(const uint32_t*)&sAlo[ra + 8];
                alo[i][3] = *(const uint32_t*)&sAlo[ra + 8 * HSTRIDE + 8];
            }
#pragma unroll
            for (int j = 0; j < 4; j++) {
                int rb = (wn * 32 + j * 8 + grp) * HSTRIDE + kb + qt * 2;
                bhi[j][0] = *(const uint32_t*)&sBhi[rb];
                bhi[j][1] = *(const uint32_t*)&sBhi[rb + 8];
                blo[j][0] = *(const uint32_t*)&sBlo[rb];
                blo[j][1] = *(const uint32_t*)&sBlo[rb + 8];
            }
#pragma unroll
            for (int i = 0; i < 2; i++)
#pragma unroll
                for (int j = 0; j < 4; j++) {
                    mma_bf16(acc[i][j], ahi[i], bhi[j]);
                    mma_bf16(acc[i][j], ahi[i], blo[j]);
                    mma_bf16(acc[i][j], alo[i], bhi[j]);
                }
        }
        if (c < 7) CVTSTORE(cur ^ 1);
        __syncthreads();
    }
#undef LOADG
#undef CVTSTORE

#pragma unroll
    for (int i = 0; i < 2; i++) {
#pragma unroll
        for (int h = 0; h < 2; h++) {
            int row = mBase + wm * 32 + i * 16 + grp + h * 8;
            if (row >= M) continue;
#pragma unroll
            for (int j = 0; j < 4; j++) {
                int col = nBase + wn * 32 + j * 8 + qt * 2;
                float v0 = acc[i][j][h * 2 + 0] + bias[col];
                float v1 = acc[i][j][h * 2 + 1] + bias[col + 1];
                v0 = fmaxf(v0, 0.f);
                v1 = fmaxf(v1, 0.f);
                if (prev) {
                    float2 pv = *(const float2*)&prev[(long)row * kD + col];
                    v0 += pv.x; v1 += pv.y;
                }
                float2 o; o.x = v0; o.y = v1;
                *(float2*)&out[(long)row * kD + col] = o;
            }
        }
    }
}

// ---------------- pooling: segmented reduction over sorted batch ids ----------------
static constexpr int PCH = 512;
__global__ void k_pool_nodes(const float* __restrict__ x, const int* __restrict__ batch,
                             float* __restrict__ sum, float* __restrict__ cnt, int N)
{
    int n0 = blockIdx.x * PCH;
    int n1 = min(N, n0 + PCH);
    int d = threadIdx.x;
    float acc = 0.f;
    int curb = __ldg(&batch[n0]);
    for (int n = n0; n < n1; n++) {
        int b = __ldg(&batch[n]);
        if (b != curb) {
            atomicAdd(&sum[curb * kD + d], acc);
            acc = 0.f;
            curb = b;
        }
        acc += x[(long)n * kD + d];
    }
    atomicAdd(&sum[curb * kD + d], acc);
    if (d == 0) {
        int c = 0;
        curb = __ldg(&batch[n0]);
        for (int n = n0; n < n1; n++) {
            int b = __ldg(&batch[n]);
            if (b != curb) { atomicAdd(&cnt[curb], (float)c); c = 0; curb = b; }
            c++;
        }
        atomicAdd(&cnt[curb], (float)c);
    }
}

// smem-accumulated edge pooling
static constexpr int PE_SMEM = (kB * 32 + kB) * 4;
__global__ void k_pool_edges(const float* __restrict__ ea, const int* __restrict__ src,
                             const int* __restrict__ hbatch,
                             const float* __restrict__ Wm, const float* __restrict__ bm,
                             float* __restrict__ esum, float* __restrict__ ecnt)
{
    extern __shared__ float sm[];
    float* ss = sm;
    float* sc = sm + kB * 32;
    for (int i = threadIdx.x; i < kB * 32 + kB; i += blockDim.x) sm[i] = 0.f;
    __syncthreads();
    for (int e = blockIdx.x * blockDim.x + threadIdx.x; e < kE; e += gridDim.x * blockDim.x) {
        float e0 = ea[2 * e], e1 = ea[2 * e + 1];
        int b = hbatch[src[e]];
        atomicAdd(&sc[b], 1.f);
#pragma unroll
        for (int j = 0; j < 32; j++) {
            float v = fmaxf(e0 * Wm[j] + e1 * Wm[32 + j] + bm[j], 0.f);
            atomicAdd(&ss[b * 32 + j], v);
        }
    }
    __syncthreads();
    for (int i = threadIdx.x; i < kB * 32; i += blockDim.x)
        if (ss[i] != 0.f) atomicAdd(&esum[i], ss[i]);
    for (int i = threadIdx.x; i < kB; i += blockDim.x)
        if (sc[i] != 0.f) atomicAdd(&ecnt[i], sc[i]);
}

// ---------------- final: graph emb -> 2 softmax heads ----------------
__global__ void k_final(const float* __restrict__ hsum, const float* __restrict__ hcnt,
                        const float* __restrict__ osum, const float* __restrict__ ocnt,
                        const float* __restrict__ esum, const float* __restrict__ ecnt,
                        const float* __restrict__ Wp1, const float* __restrict__ bp1,
                        const float* __restrict__ Wp2, const float* __restrict__ bp2,
                        float* __restrict__ out)
{
    __shared__ float emb[2 * kD + 32];
    __shared__ float red[128];
    int b = blockIdx.x, t = threadIdx.x;
    float hc = fmaxf(hcnt[b], 1.f), oc = fmaxf(ocnt[b], 1.f), ec = fmaxf(ecnt[b], 1.f);
    for (int k = t; k < kD; k += 128) {
        emb[k]      = hsum[b * kD + k] / hc;
        emb[kD + k] = osum[b * kD + k] / oc;
    }
    for (int k = t; k < 32; k += 128) emb[2 * kD + k] = esum[b * 32 + k] / ec;
    __syncthreads();

    for (int head = 0; head < 2; head++) {
        const float* W  = head ? Wp2 : Wp1;
        const float* bb = head ? bp2 : bp1;
        float v = -3.0e38f;
        if (t < kC) {
            v = bb[t];
            for (int k = 0; k < 2 * kD + 32; k++) v += emb[k] * W[k * kC + t];
        }
        red[t] = v;
        __syncthreads();
        for (int s = 64; s > 0; s >>= 1) {
            if (t < s) red[t] = fmaxf(red[t], red[t + s]);
            __syncthreads();
        }
        float mx = red[0];
        __syncthreads();
        float ex = (t < kC) ? expf(v - mx) : 0.f;
        red[t] = ex;
        __syncthreads();
        for (int s = 64; s > 0; s >>= 1) {
            if (t < s) red[t] += red[t + s];
            __syncthreads();
        }
        float sm = red[0];
        __syncthreads();
        if (t < kC) out[(b * 2 + head) * kC + t] = ex / sm;
    }
}

// ---------------- launch ----------------
extern "C" void kernel_launch(void* const* d_in, const int* in_sizes, int n_in,
                              void* d_out, int out_size)
{
    const float* x_human = (const float*)d_in[0];
    const float* x_object = (const float*)d_in[1];
    const int* ei_ho = (const int*)d_in[2];
    const int* ei_oh = (const int*)d_in[3];
    const float* ea_ho = (const float*)d_in[4];
    const float* ea_oh = (const float*)d_in[5];
    const int* hbatch = (const int*)d_in[6];
    const int* obatch = (const int*)d_in[7];
    const float* Wsrc_ho = (const float*)d_in[8];
    const float* Wdst_ho = (const float*)d_in[9];
    const float* asrc_ho = (const float*)d_in[10];
    const float* adst_ho = (const float*)d_in[11];
    const float* Wedge_ho = (const float*)d_in[12];
    const float* aedge_ho = (const float*)d_in[13];
    const float* bias_ho = (const float*)d_in[14];
    const float* Wsrc_oh = (const float*)d_in[15];
    const float* Wdst_oh = (const float*)d_in[16];
    const float* asrc_oh = (const float*)d_in[17];
    const float* adst_oh = (const float*)d_in[18];
    const float* Wedge_oh = (const float*)d_in[19];
    const float* aedge_oh = (const float*)d_in[20];
    const float* bias_oh = (const float*)d_in[21];
    const float* W_emlp = (const float*)d_in[22];
    const float* b_emlp = (const float*)d_in[23];
    const float* W_p1 = (const float*)d_in[24];
    const float* b_p1 = (const float*)d_in[25];
    const float* W_p2 = (const float*)d_in[26];
    const float* b_p2 = (const float*)d_in[27];

    float *h0, *h1, *o0, *o1, *agg0, *agg1;
    float *aSho, *aDoh, *aDho, *aSoh, *vsrc, *vdst, *ced;
    float *hsum, *osum, *esum, *hcnt, *ocnt, *ecnt;
    float2* ea2;
    int *srcs;
    __nv_bfloat16* wTb;
    int *off, *eid, *cur, *part;
    cudaGetSymbolAddress((void**)&h0, g_h0);
    cudaGetSymbolAddress((void**)&h1, g_h1);
    cudaGetSymbolAddress((void**)&o0, g_o0);
    cudaGetSymbolAddress((void**)&o1, g_o1);
    cudaGetSymbolAddress((void**)&agg0, g_agg0);
    cudaGetSymbolAddress((void**)&agg1, g_agg1);
    cudaGetSymbolAddress((void**)&aSho, g_aSho);
    cudaGetSymbolAddress((void**)&aDoh, g_aDoh);
    cudaGetSymbolAddress((void**)&aDho, g_aDho);
    cudaGetSymbolAddress((void**)&aSoh, g_aSoh);
    cudaGetSymbolAddress((void**)&vsrc, g_vsrc);
    cudaGetSymbolAddress((void**)&vdst, g_vdst);
    cudaGetSymbolAddress((void**)&ced, g_cedge);
    cudaGetSymbolAddress((void**)&wTb, g_wTb);
    cudaGetSymbolAddress((void**)&off, g_off);
    cudaGetSymbolAddress((void**)&eid, g_eid);
    cudaGetSymbolAddress((void**)&cur, g_cursor);
    cudaGetSymbolAddress((void**)&part, g_part);
    cudaGetSymbolAddress((void**)&srcs, g_srcs);
    cudaGetSymbolAddress((void**)&ea2, g_ea2);
    cudaGetSymbolAddress((void**)&hsum, g_hsum);
    cudaGetSymbolAddress((void**)&osum, g_osum);
    cudaGetSymbolAddress((void**)&esum, g_esum);
    cudaGetSymbolAddress((void**)&hcnt, g_hcnt);
    cudaGetSymbolAddress((void**)&ocnt, g_ocnt);
    cudaGetSymbolAddress((void**)&ecnt, g_ecnt);

    cudaFuncSetAttribute(k_gemm_mma, cudaFuncAttributeMaxDynamicSharedMemorySize, GEMM_SMEM);
    cudaFuncSetAttribute(k_pool_edges, cudaFuncAttributeMaxDynamicSharedMemorySize, PE_SMEM);

    const int EB = (kE + 255) / 256;
    const dim3 GEMM_GRID(2, (kNH + 127) / 128, 2);

    // ---- CSR build for both relations ----
    cudaMemsetAsync(cur, 0, sizeof(int) * 2 * kNH);
    k_hist<<<dim3(EB, 2), 256>>>(ei_ho + kE, ei_oh + kE, cur);
    k_scan_part<<<dim3(NCHUNK, 2), 256>>>(cur, part);
    k_scan_apply<<<dim3(NCHUNK, 2), 256>>>(cur, off, part);
    k_scatter<<<dim3(EB, 2), 256>>>(ei_ho + kE, ei_oh + kE, cur, eid);
    k_edgeprep<<<dim3(EB, 2), 256>>>(eid, ei_ho, ei_oh, ea_ho, ea_oh, srcs, ea2);

    // ---- per-layer precompute ----
    k_precompute<<<2 * kL, 256>>>(Wsrc_ho, asrc_ho, Wdst_ho, adst_ho, Wedge_ho, aedge_ho,
                                  Wsrc_oh, asrc_oh, Wdst_oh, adst_oh, Wedge_oh, aedge_oh);
    k_wprep<<<dim3(16, 64), dim3(32, 8)>>>(Wsrc_ho, Wsrc_oh);

    // ---- 8 layers ----
    const float* cur_h = x_human;
    const float* cur_o = x_object;
    for (int l = 0; l < kL; l++) {
        float* nh = (l & 1) ? h1 : h0;
        float* no = (l & 1) ? o1 : o0;

        k_matvec2_dual<<<(kNH + kNO) / 8, 256>>>(
            cur_h, cur_o,
            vsrc + (0 * kL + l) * kD, vdst + (1 * kL + l) * kD,
            vdst + (0 * kL + l) * kD, vsrc + (1 * kL + l) * kD,
            aSho, aDoh, aDho, aSoh);

        k_aggregate_dual<<<(kNO + kNH) / 8, 256>>>(
            off, srcs, ea2,
            aSho, aDho, cur_h, ced + (0 * kL + l) * 2, agg0,
            aSoh, aDoh, cur_o, ced + (1 * kL + l) * 2, agg1);

        k_gemm_mma<<<GEMM_GRID, 512, GEMM_SMEM>>>(
            agg0, agg1,
            wTb + (long)(0 * kL + l) * 2 * kD * kD, wTb + (long)(1 * kL + l) * 2 * kD * kD,
            bias_ho + l * kD, bias_oh + l * kD,
            l ? cur_o : nullptr, l ? cur_h : nullptr,
            no, nh, kNO);

        cur_h = nh;
        cur_o = no;
    }

    // ---- pooling ----
    cudaMemsetAsync(hsum, 0, sizeof(float) * kB * kD);
    cudaMemsetAsync(osum, 0, sizeof(float) * kB * kD);
    cudaMemsetAsync(esum, 0, sizeof(float) * kB * 32);
    cudaMemsetAsync(hcnt, 0, sizeof(float) * kB);
    cudaMemsetAsync(ocnt, 0, sizeof(float) * kB);
    cudaMemsetAsync(ecnt, 0, sizeof(float) * kB);
    k_pool_nodes<<<(kNH + PCH - 1) / PCH, 256>>>(cur_h, hbatch, hsum, hcnt, kNH);
    k_pool_nodes<<<(kNO + PCH - 1) / PCH, 256>>>(cur_o, obatch, osum, ocnt, kNO);
    k_pool_edges<<<132, 256, PE_SMEM>>>(ea_ho, ei_ho, hbatch, W_emlp, b_emlp, esum, ecnt);

    // ---- classifier heads ----
    k_final<<<kB, 128>>>(hsum, hcnt, osum, ocnt, esum, ecnt,
                         W_p1, b_p1, W_p2, b_p2, (float*)d_out);
}

// round 12
// speedup vs baseline: 1.6578x; 1.0044x over previous
#include <cuda_runtime.h>
#include <cuda_bf16.h>
#include <cstdint>

static constexpr int kNH = 50000;
static constexpr int kNO = 50000;
static constexpr int kE  = 500000;
static constexpr int kD  = 256;
static constexpr int kL  = 8;
static constexpr int kB  = 512;
static constexpr int kC  = 117;
static constexpr int kPadRows = 128;

// ---------------- device scratch (static, no runtime alloc) ----------------
__device__ float g_h0[kNH * kD];
__device__ float g_h1[kNH * kD];
__device__ float g_o0[kNO * kD];
__device__ float g_o1[kNO * kD];

// aggregate output as bf16 hi/lo planes (padded rows stay zero forever)
__device__ __nv_bfloat16 g_a0hi[(kNO + kPadRows) * kD];
__device__ __nv_bfloat16 g_a0lo[(kNO + kPadRows) * kD];
__device__ __nv_bfloat16 g_a1hi[(kNH + kPadRows) * kD];
__device__ __nv_bfloat16 g_a1lo[(kNH + kPadRows) * kD];

__device__ float g_aSho[kNH], g_aDoh[kNH], g_aDho[kNO], g_aSoh[kNO];

__device__ float g_vsrc[2 * kL * kD];
__device__ float g_vdst[2 * kL * kD];
__device__ float g_cedge[2 * kL * 2];

// W^T as bf16 hi/lo: [rel*8+layer][hi/lo][n=256][k=256]
__device__ __nv_bfloat16 g_wTb[2 * kL * 2 * kD * kD];

static constexpr int SCHUNK = 4096;
static constexpr int NCHUNK = (kNH + SCHUNK - 1) / SCHUNK;  // 13

__device__ int g_cnt[2 * kNH];
__device__ int g_off[2 * (kNH + 1)];
__device__ int g_cursor[2 * kNH];

// CSR-ordered edge data: source node id + edge attrs
__device__ int    g_srcs[2 * kE];
__device__ float2 g_ea2[2 * kE];

__device__ float g_hsum[kB * kD], g_osum[kB * kD], g_esum[kB * 32];
__device__ float g_hcnt[kB], g_ocnt[kB], g_ecnt[kB];

__device__ __forceinline__ uint32_t pack2(__nv_bfloat16 a, __nv_bfloat16 b) {
    return (uint32_t)__bfloat16_as_ushort(a) | ((uint32_t)__bfloat16_as_ushort(b) << 16);
}
__device__ __forceinline__ void cvt_split(float4 v, uint2& h, uint2& l) {
    __nv_bfloat16 hx = __float2bfloat16(v.x), hy = __float2bfloat16(v.y);
    __nv_bfloat16 hz = __float2bfloat16(v.z), hw = __float2bfloat16(v.w);
    __nv_bfloat16 lx = __float2bfloat16(v.x - __bfloat162float(hx));
    __nv_bfloat16 ly = __float2bfloat16(v.y - __bfloat162float(hy));
    __nv_bfloat16 lz = __float2bfloat16(v.z - __bfloat162float(hz));
    __nv_bfloat16 lw = __float2bfloat16(v.w - __bfloat162float(hw));
    h.x = pack2(hx, hy); h.y = pack2(hz, hw);
    l.x = pack2(lx, ly); l.y = pack2(lz, lw);
}
__device__ __forceinline__ uint32_t smem_u32(const void* p) {
    uint32_t a;
    asm("{ .reg .u64 t; cvta.to.shared.u64 t, %1; cvt.u32.u64 %0, t; }" : "=r"(a) : "l"(p));
    return a;
}
#define CP8(dst, src) \
    asm volatile("cp.async.ca.shared.global [%0], [%1], 8;" :: "r"(dst), "l"(src) : "memory")

// ============================================================================
// fused: per-layer attention-vector precompute (blocks 0..15) + cnt zeroing
// ============================================================================
__global__ void k_prep(
    const float* __restrict__ Wsrc0, const float* __restrict__ asrc0,
    const float* __restrict__ Wdst0, const float* __restrict__ adst0,
    const float* __restrict__ Wedge0, const float* __restrict__ aedge0,
    const float* __restrict__ Wsrc1, const float* __restrict__ asrc1,
    const float* __restrict__ Wdst1, const float* __restrict__ adst1,
    const float* __restrict__ Wedge1, const float* __restrict__ aedge1,
    int* __restrict__ cnt)
{
    if (blockIdx.x >= 16) {
        int idx = (blockIdx.x - 16) * 256 + threadIdx.x;
        if (idx < 2 * kNH) cnt[idx] = 0;
        return;
    }
    int rel = blockIdx.x / kL;
    int l   = blockIdx.x % kL;
    const float* Wsrc  = rel ? Wsrc1  : Wsrc0;
    const float* asrc  = rel ? asrc1  : asrc0;
    const float* Wdst  = rel ? Wdst1  : Wdst0;
    const float* adst  = rel ? adst1  : adst0;
    const float* Wedge = rel ? Wedge1 : Wedge0;
    const float* aedge = rel ? aedge1 : aedge0;

    int i = threadIdx.x;
    float s1 = 0.f, s2 = 0.f;
    const float* wsr = Wsrc + (long)l * kD * kD + (long)i * kD;
    const float* wdr = Wdst + (long)l * kD * kD + (long)i * kD;
    const float* as  = asrc + l * kD;
    const float* ad  = adst + l * kD;
    for (int j = 0; j < kD; j++) { s1 += wsr[j] * as[j]; s2 += wdr[j] * ad[j]; }
    g_vsrc[(rel * kL + l) * kD + i] = s1;
    g_vdst[(rel * kL + l) * kD + i] = s2;
    if (i < 2) {
        float c = 0.f;
        const float* we = Wedge + (long)l * 2 * kD + (long)i * kD;
        const float* ae = aedge + l * kD;
        for (int j = 0; j < kD; j++) c += we[j] * ae[j];
        g_cedge[(rel * kL + l) * 2 + i] = c;
    }
}

// ---------------- transpose + bf16 hi/lo split of Wsrc weights ----------------
__global__ void k_wprep(const float* __restrict__ W_ho, const float* __restrict__ W_oh)
{
    int rl = blockIdx.x;
    int rel = rl >> 3;
    const float* W = (rel ? W_oh : W_ho) + (long)(rl & 7) * kD * kD;
    int tile = blockIdx.y;
    int tk = (tile & 7) * 32, tn = (tile >> 3) * 32;
    __shared__ float s[32][33];
    int tx = threadIdx.x, ty = threadIdx.y;
    for (int yy = ty; yy < 32; yy += 8)
        s[yy][tx] = W[(long)(tk + yy) * kD + tn + tx];
    __syncthreads();
    __nv_bfloat16* outHi = g_wTb + (long)rl * 2 * kD * kD;
    __nv_bfloat16* outLo = outHi + kD * kD;
    for (int yy = ty; yy < 32; yy += 8) {
        float v = s[tx][yy];
        __nv_bfloat16 h = __float2bfloat16(v);
        __nv_bfloat16 l = __float2bfloat16(v - __bfloat162float(h));
        outHi[(long)(tn + yy) * kD + tk + tx] = h;
        outLo[(long)(tn + yy) * kD + tk + tx] = l;
    }
}

// ---------------- CSR build ----------------
__global__ void k_hist(const int* __restrict__ d0, const int* __restrict__ d1,
                       int* __restrict__ cnt)
{
    int e = blockIdx.x * blockDim.x + threadIdx.x;
    if (e >= kE) return;
    int rel = blockIdx.y;
    const int* d = rel ? d1 : d0;
    atomicAdd(&cnt[rel * kNH + d[e]], 1);
}

// single-pass scan: block computes its carry from the read-only histogram
__global__ void k_scan(const int* __restrict__ cnt, int* __restrict__ off,
                       int* __restrict__ cursor)
{
    int rel = blockIdx.y, ch = blockIdx.x;
    const int* cc = cnt + rel * kNH;
    int* oo = off + rel * (kNH + 1);
    int* uu = cursor + rel * kNH;
    int start = ch * SCHUNK;
    int n = min(SCHUNK, kNH - start);
    int t = threadIdx.x, lane = t & 31, wid = t >> 5;
    __shared__ int wsum[8];
    __shared__ int s_carry;

    int s = 0;
    for (int i = t; i < start; i += 256) s += cc[i];
#pragma unroll
    for (int o = 16; o > 0; o >>= 1) s += __shfl_xor_sync(0xffffffffu, s, o);
    if (lane == 0) wsum[wid] = s;
    __syncthreads();
    if (t == 0) {
        int tot = 0;
        for (int k = 0; k < 8; k++) tot += wsum[k];
        s_carry = tot;
    }
    __syncthreads();
    int carry = s_carry;
    __syncthreads();

    for (int b0 = 0; b0 < n; b0 += 256) {
        int i = start + b0 + t;
        int c = (b0 + t < n) ? cc[i] : 0;
        int v = c;
#pragma unroll
        for (int o = 1; o < 32; o <<= 1) {
            int u = __shfl_up_sync(0xffffffffu, v, o);
            if (lane >= o) v += u;
        }
        if (lane == 31) wsum[wid] = v;
        __syncthreads();
        int wpre = 0, btot = 0;
#pragma unroll
        for (int k = 0; k < 8; k++) {
            int ws = wsum[k];
            if (k < wid) wpre += ws;
            btot += ws;
        }
        int excl = carry + (v - c) + wpre;
        if (b0 + t < n) { oo[i] = excl; uu[i] = excl; }
        carry += btot;
        __syncthreads();
    }
    if (t == 0 && ch == 0) oo[kNH] = kE;
}

// scatter + edge permutation fused
__global__ void k_scatter(const int* __restrict__ d0, const int* __restrict__ d1,
                          const int* __restrict__ s0, const int* __restrict__ s1,
                          const float* __restrict__ ea0, const float* __restrict__ ea1,
                          int* __restrict__ cur, int* __restrict__ srcs,
                          float2* __restrict__ ea2)
{
    int e = blockIdx.x * blockDim.x + threadIdx.x;
    if (e >= kE) return;
    int rel = blockIdx.y;
    const int* d = rel ? d1 : d0;
    const int* sp = rel ? s1 : s0;
    const float* ea = rel ? ea1 : ea0;
    int p = atomicAdd(&cur[rel * kNH + d[e]], 1);
    srcs[rel * kE + p] = sp[e];
    ea2[rel * kE + p] = make_float2(ea[2 * e], ea[2 * e + 1]);
}

// ---------------- fused dual matvec (float4) ----------------
__global__ void k_matvec2_dual(const float* __restrict__ xh, const float* __restrict__ xo,
                               const float* __restrict__ vh1, const float* __restrict__ vh2,
                               const float* __restrict__ vo1, const float* __restrict__ vo2,
                               float* __restrict__ aSho, float* __restrict__ aDoh,
                               float* __restrict__ aDho, float* __restrict__ aSoh)
{
    int gw = (blockIdx.x * blockDim.x + threadIdx.x) >> 5;
    int lane = threadIdx.x & 31;
    if (gw >= kNH + kNO) return;
    int rel = gw >= kNH;
    int w = rel ? gw - kNH : gw;
    const float* x  = rel ? xo  : xh;
    const float4* v1 = (const float4*)(rel ? vo1 : vh1);
    const float4* v2 = (const float4*)(rel ? vo2 : vh2);
    float* o1 = rel ? aDho : aSho;
    float* o2 = rel ? aSoh : aDoh;

    const float4* xr = (const float4*)(x + (long)w * kD);
    float4 xa = xr[lane], xb = xr[lane + 32];
    float4 va = v1[lane], vb = v1[lane + 32];
    float4 wa = v2[lane], wb = v2[lane + 32];
    float s1 = xa.x * va.x + xa.y * va.y + xa.z * va.z + xa.w * va.w
             + xb.x * vb.x + xb.y * vb.y + xb.z * vb.z + xb.w * vb.w;
    float s2 = xa.x * wa.x + xa.y * wa.y + xa.z * wa.z + xa.w * wa.w
             + xb.x * wb.x + xb.y * wb.y + xb.z * wb.z + xb.w * wb.w;
#pragma unroll
    for (int o = 16; o > 0; o >>= 1) {
        s1 += __shfl_xor_sync(0xffffffffu, s1, o);
        s2 += __shfl_xor_sync(0xffffffffu, s2, o);
    }
    if (lane == 0) { o1[w] = s1; o2[w] = s2; }
}

// ---------------- dual segment softmax + gather-aggregate; writes bf16 hi/lo ----------------
__global__ void k_aggregate_dual(
    const int* __restrict__ off, const int* __restrict__ srcs,
    const float2* __restrict__ ea2,
    const float* __restrict__ aS0, const float* __restrict__ aD0,
    const float* __restrict__ x0, const float* __restrict__ ced0,
    __nv_bfloat16* __restrict__ a0hi, __nv_bfloat16* __restrict__ a0lo,
    const float* __restrict__ aS1, const float* __restrict__ aD1,
    const float* __restrict__ x1, const float* __restrict__ ced1,
    __nv_bfloat16* __restrict__ a1hi, __nv_bfloat16* __restrict__ a1lo)
{
    int gw = (blockIdx.x * blockDim.x + threadIdx.x) >> 5;
    int lane = threadIdx.x & 31;
    if (gw >= kNO + kNH) return;
    int rel = gw >= kNO;
    int w = rel ? gw - kNO : gw;
    const int* o     = off + rel * (kNH + 1);
    const int* sc    = srcs + rel * kE;
    const float2* e2 = ea2 + rel * kE;
    const float* aS  = rel ? aS1 : aS0;
    const float* aD  = rel ? aD1 : aD0;
    const float* x   = rel ? x1 : x0;
    const float* ced = rel ? ced1 : ced0;
    __nv_bfloat16* ahi = rel ? a1hi : a0hi;
    __nv_bfloat16* alo = rel ? a1lo : a0lo;

    int beg = o[w], end = o[w + 1];
    int deg = end - beg;
    float c0 = ced[0], c1 = ced[1];
    float ad = aD[w];

    float4 acc0 = make_float4(0.f, 0.f, 0.f, 0.f);
    float4 acc1 = make_float4(0.f, 0.f, 0.f, 0.f);

    if (deg <= 128) {
        int sid[4];
        float ex[4];
        float m = -3.0e38f;
#pragma unroll
        for (int s = 0; s < 4; s++) {
            int i = beg + lane + 32 * s;
            bool ok = i < end;
            sid[s] = ok ? sc[i] : 0;
            float lg = -3.0e38f;
            if (ok) {
                float2 e = e2[i];
                lg = aS[sid[s]] + ad + c0 * e.x + c1 * e.y;
                lg = lg > 0.f ? lg : 0.2f * lg;
            }
            ex[s] = lg;
            m = fmaxf(m, lg);
        }
#pragma unroll
        for (int o2 = 16; o2 > 0; o2 >>= 1) m = fmaxf(m, __shfl_xor_sync(0xffffffffu, m, o2));

        float den = 0.f;
#pragma unroll
        for (int s = 0; s < 4; s++) {
            float e_ = (beg + lane + 32 * s < end) ? expf(ex[s] - m) : 0.f;
            ex[s] = e_;
            den += e_;
        }
#pragma unroll
        for (int o2 = 16; o2 > 0; o2 >>= 1) den += __shfl_xor_sync(0xffffffffu, den, o2);
        float inv = (den > 0.f) ? 1.f / den : 0.f;

#pragma unroll
        for (int s = 0; s < 4; s++) {
            int base = beg + 32 * s;
            int cnt = min(32, end - base);
            if (cnt <= 0) break;
            float wts = ex[s] * inv;
            for (int t = 0; t < cnt; t++) {
                float wt = __shfl_sync(0xffffffffu, wts, t);
                int sb   = __shfl_sync(0xffffffffu, sid[s], t);
                const float4* xr = (const float4*)(x + (long)sb * kD);
                float4 xa = xr[lane];
                float4 xb = xr[lane + 32];
                acc0.x += wt * xa.x; acc0.y += wt * xa.y;
                acc0.z += wt * xa.z; acc0.w += wt * xa.w;
                acc1.x += wt * xb.x; acc1.y += wt * xb.y;
                acc1.z += wt * xb.z; acc1.w += wt * xb.w;
            }
        }
    } else {
        float m = -3.0e38f;
        for (int i = beg + lane; i < end; i += 32) {
            float2 e = e2[i];
            float lg = aS[sc[i]] + ad + c0 * e.x + c1 * e.y;
            lg = lg > 0.f ? lg : 0.2f * lg;
            m = fmaxf(m, lg);
        }
#pragma unroll
        for (int o2 = 16; o2 > 0; o2 >>= 1) m = fmaxf(m, __shfl_xor_sync(0xffffffffu, m, o2));
        float den = 0.f;
        for (int i = beg + lane; i < end; i += 32) {
            float2 e = e2[i];
            float lg = aS[sc[i]] + ad + c0 * e.x + c1 * e.y;
            lg = lg > 0.f ? lg : 0.2f * lg;
            den += expf(lg - m);
        }
#pragma unroll
        for (int o2 = 16; o2 > 0; o2 >>= 1) den += __shfl_xor_sync(0xffffffffu, den, o2);
        float inv = (den > 0.f) ? 1.f / den : 0.f;
        for (int i = beg; i < end; i++) {
            float2 e = e2[i];
            int sb = sc[i];
            float lg = aS[sb] + ad + c0 * e.x + c1 * e.y;
            lg = lg > 0.f ? lg : 0.2f * lg;
            float wt = expf(lg - m) * inv;
            const float4* xr = (const float4*)(x + (long)sb * kD);
            float4 xa = xr[lane];
            float4 xb = xr[lane + 32];
            acc0.x += wt * xa.x; acc0.y += wt * xa.y;
            acc0.z += wt * xa.z; acc0.w += wt * xa.w;
            acc1.x += wt * xb.x; acc1.y += wt * xb.y;
            acc1.z += wt * xb.z; acc1.w += wt * xb.w;
        }
    }

    uint2 h0, l0, h1, l1;
    cvt_split(acc0, h0, l0);
    cvt_split(acc1, h1, l1);
    uint2* rh = (uint2*)(ahi + (long)w * kD);
    uint2* rl = (uint2*)(alo + (long)w * kD);
    rh[lane] = h0; rh[lane + 32] = h1;
    rl[lane] = l0; rl[lane + 32] = l1;
}

// ============================================================================
// mma.sync bf16 GEMM (3xBF16), cp.async double-buffered; A pre-split bf16 planes.
// ============================================================================
static constexpr int HSTRIDE = 40;
static constexpr int BUFH = 4 * 128 * HSTRIDE;        // halfs per stage
static constexpr int GEMM_SMEM = 2 * BUFH * 2;        // 81920 B

__device__ __forceinline__ void mma_bf16(float* c, const uint32_t* a, const uint32_t* b) {
    asm volatile(
        "mma.sync.aligned.m16n8k16.row.col.f32.bf16.bf16.f32 "
        "{%0,%1,%2,%3}, {%4,%5,%6,%7}, {%8,%9}, {%0,%1,%2,%3};\n"
        : "+f"(c[0]), "+f"(c[1]), "+f"(c[2]), "+f"(c[3])
        : "r"(a[0]), "r"(a[1]), "r"(a[2]), "r"(a[3]), "r"(b[0]), "r"(b[1]));
}

__global__ void __launch_bounds__(512) k_gemm_mma(
    const __nv_bfloat16* __restrict__ A0hi, const __nv_bfloat16* __restrict__ A0lo,
    const __nv_bfloat16* __restrict__ A1hi, const __nv_bfloat16* __restrict__ A1lo,
    const __nv_bfloat16* __restrict__ WT0, const __nv_bfloat16* __restrict__ WT1,
    const float* __restrict__ bias0, const float* __restrict__ bias1,
    const float* __restrict__ prev0, const float* __restrict__ prev1,
    float* __restrict__ out0, float* __restrict__ out1, int M)
{
    extern __shared__ __nv_bfloat16 smh[];
    const uint32_t sb = smem_u32(smh);

    const int z = blockIdx.z;
    const __nv_bfloat16* Ahi = z ? A1hi : A0hi;
    const __nv_bfloat16* Alo = z ? A1lo : A0lo;
    const __nv_bfloat16* WT = z ? WT1 : WT0;
    const float* bias = z ? bias1 : bias0;
    const float* prev = z ? prev1 : prev0;
    float* out = z ? out1 : out0;

    const int tid = threadIdx.x;
    const int w = tid >> 5, lane = tid & 31;
    const int wm = w & 3, wn = w >> 2;
    const int grp = lane >> 2, qt = lane & 3;
    const int mBase = blockIdx.y * 128;
    const int nBase = blockIdx.x * 128;

    const __nv_bfloat16* WThi = WT + (long)nBase * kD;
    const __nv_bfloat16* WTlo = WT + (long)kD * kD + (long)nBase * kD;

    const int r0 = tid >> 3, q0 = tid & 7;
    const long gA0 = (long)(mBase + r0) * kD + q0 * 4;
    const long gA1 = (long)(mBase + r0 + 64) * kD + q0 * 4;
    const long gB0 = (long)r0 * kD + q0 * 4;
    const long gB1 = (long)(r0 + 64) * kD + q0 * 4;
    const uint32_t dOff0 = 2 * (r0 * HSTRIDE + q0 * 4);
    const uint32_t dOff1 = 2 * ((r0 + 64) * HSTRIDE + q0 * 4);
    const uint32_t PL = 2 * 128 * HSTRIDE;  // plane size in bytes

    float acc[2][4][4];
#pragma unroll
    for (int i = 0; i < 2; i++)
#pragma unroll
        for (int j = 0; j < 4; j++)
#pragma unroll
            for (int q = 0; q < 4; q++) acc[i][j][q] = 0.f;

#define ISSUE(c, buf)                                                   \
    do {                                                                \
        uint32_t base = sb + (uint32_t)(buf) * (BUFH * 2);              \
        long ko = (long)(c) * 32;                                       \
        CP8(base + dOff0, Ahi + gA0 + ko);                              \
        CP8(base + dOff1, Ahi + gA1 + ko);                              \
        CP8(base + PL + dOff0, Alo + gA0 + ko);                         \
        CP8(base + PL + dOff1, Alo + gA1 + ko);                         \
        CP8(base + 2 * PL + dOff0, WThi + gB0 + ko);                    \
        CP8(base + 2 * PL + dOff1, WThi + gB1 + ko);                    \
        CP8(base + 3 * PL + dOff0, WTlo + gB0 + ko);                    \
        CP8(base + 3 * PL + dOff1, WTlo + gB1 + ko);                    \
        asm volatile("cp.async.commit_group;" ::: "memory");            \
    } while (0)

    ISSUE(0, 0);

#pragma unroll 1
    for (int c = 0; c < 8; c++) {
        const int cur = c & 1;
        if (c < 7) {
            ISSUE(c + 1, cur ^ 1);
            asm volatile("cp.async.wait_group 1;" ::: "memory");
        } else {
            asm volatile("cp.async.wait_group 0;" ::: "memory");
        }
        __syncthreads();

        const __nv_bfloat16* sAhi = smh + cur * BUFH;
        const __nv_bfloat16* sAlo = sAhi + 128 * HSTRIDE;
        const __nv_bfloat16* sBhi = sAhi + 2 * 128 * HSTRIDE;
        const __nv_bfloat16* sBlo = sAhi + 3 * 128 * HSTRIDE;
#pragma unroll
        for (int ks = 0; ks < 2; ks++) {
            int kb = ks * 16;
            uint32_t ahi[2][4], alo[2][4], bhi[4][2], blo[4][2];
#pragma unroll
            for (int i = 0; i < 2; i++) {
                int ra = (wm * 32 + i * 16 + grp) * HSTRIDE + kb + qt * 2;
                ahi[i][0] = *(const uint32_t*)&sAhi[ra];
                ahi[i][1] = *(const uint32_t*)&sAhi[ra + 8 * HSTRIDE];
                ahi[i][2] = *(const uint32_t*)&sAhi[ra + 8];
                ahi[i][3] = *(const uint32_t*)&sAhi[ra + 8 * HSTRIDE + 8];
                alo[i][0] = *(const uint32_t*)&sAlo[ra];
                alo[i][1] = *(const uint32_t*)&sAlo[ra + 8 * HSTRIDE];
                alo[i][2] = *(const uint32_t*)&sAlo[ra + 8];
                alo[i][3] = *(const uint32_t*)&sAlo[ra + 8 * HSTRIDE + 8];
            }
#pragma unroll
            for (int j = 0; j < 4; j++) {
                int rb = (wn * 32 + j * 8 + grp) * HSTRIDE + kb + qt * 2;
                bhi[j][0] = *(const uint32_t*)&sBhi[rb];
                bhi[j][1] = *(const uint32_t*)&sBhi[rb + 8];
                blo[j][0] = *(const uint32_t*)&sBlo[rb];
                blo[j][1] = *(const uint32_t*)&sBlo[rb + 8];
            }
#pragma unroll
            for (int i = 0; i < 2; i++)
#pragma unroll
                for (int j = 0; j < 4; j++) {
                    mma_bf16(acc[i][j], ahi[i], bhi[j]);
                    mma_bf16(acc[i][j], ahi[i], blo[j]);
                    mma_bf16(acc[i][j], alo[i], bhi[j]);
                }
        }
        __syncthreads();
    }
#undef ISSUE

#pragma unroll
    for (int i = 0; i < 2; i++) {
#pragma unroll
        for (int h = 0; h < 2; h++) {
            int row = mBase + wm * 32 + i * 16 + grp + h * 8;
            if (row >= M) continue;
#pragma unroll
            for (int j = 0; j < 4; j++) {
                int col = nBase + wn * 32 + j * 8 + qt * 2;
                float v0 = acc[i][j][h * 2 + 0] + bias[col];
                float v1 = acc[i][j][h * 2 + 1] + bias[col + 1];
                v0 = fmaxf(v0, 0.f);
                v1 = fmaxf(v1, 0.f);
                if (prev) {
                    float2 pv = *(const float2*)&prev[(long)row * kD + col];
                    v0 += pv.x; v1 += pv.y;
                }
                float2 o; o.x = v0; o.y = v1;
                *(float2*)&out[(long)row * kD + col] = o;
            }
        }
    }
}

// ---------------- pooling: segmented reduction over sorted batch ids ----------------
static constexpr int PCH = 512;
__global__ void k_pool_nodes(const float* __restrict__ x, const int* __restrict__ batch,
                             float* __restrict__ sum, float* __restrict__ cnt, int N)
{
    int n0 = blockIdx.x * PCH;
    int n1 = min(N, n0 + PCH);
    int d = threadIdx.x;
    float acc = 0.f;
    int curb = __ldg(&batch[n0]);
    for (int n = n0; n < n1; n++) {
        int b = __ldg(&batch[n]);
        if (b != curb) {
            atomicAdd(&sum[curb * kD + d], acc);
            acc = 0.f;
            curb = b;
        }
        acc += x[(long)n * kD + d];
    }
    atomicAdd(&sum[curb * kD + d], acc);
    if (d == 0) {
        int c = 0;
        curb = __ldg(&batch[n0]);
        for (int n = n0; n < n1; n++) {
            int b = __ldg(&batch[n]);
            if (b != curb) { atomicAdd(&cnt[curb], (float)c); c = 0; curb = b; }
            c++;
        }
        atomicAdd(&cnt[curb], (float)c);
    }
}

static constexpr int PE_SMEM = (kB * 32 + kB) * 4;
__global__ void k_pool_edges(const float* __restrict__ ea, const int* __restrict__ src,
                             const int* __restrict__ hbatch,
                             const float* __restrict__ Wm, const float* __restrict__ bm,
                             float* __restrict__ esum, float* __restrict__ ecnt)
{
    extern __shared__ float sm[];
    float* ss = sm;
    float* sc = sm + kB * 32;
    for (int i = threadIdx.x; i < kB * 32 + kB; i += blockDim.x) sm[i] = 0.f;
    __syncthreads();
    for (int e = blockIdx.x * blockDim.x + threadIdx.x; e < kE; e += gridDim.x * blockDim.x) {
        float e0 = ea[2 * e], e1 = ea[2 * e + 1];
        int b = hbatch[src[e]];
        atomicAdd(&sc[b], 1.f);
#pragma unroll
        for (int j = 0; j < 32; j++) {
            float v = fmaxf(e0 * Wm[j] + e1 * Wm[32 + j] + bm[j], 0.f);
            atomicAdd(&ss[b * 32 + j], v);
        }
    }
    __syncthreads();
    for (int i = threadIdx.x; i < kB * 32; i += blockDim.x)
        if (ss[i] != 0.f) atomicAdd(&esum[i], ss[i]);
    for (int i = threadIdx.x; i < kB; i += blockDim.x)
        if (sc[i] != 0.f) atomicAdd(&ecnt[i], sc[i]);
}

// ---------------- final: graph emb -> 2 softmax heads ----------------
__global__ void k_final(const float* __restrict__ hsum, const float* __restrict__ hcnt,
                        const float* __restrict__ osum, const float* __restrict__ ocnt,
                        const float* __restrict__ esum, const float* __restrict__ ecnt,
                        const float* __restrict__ Wp1, const float* __restrict__ bp1,
                        const float* __restrict__ Wp2, const float* __restrict__ bp2,
                        float* __restrict__ out)
{
    __shared__ float emb[2 * kD + 32];
    __shared__ float red[128];
    int b = blockIdx.x, t = threadIdx.x;
    float hc = fmaxf(hcnt[b], 1.f), oc = fmaxf(ocnt[b], 1.f), ec = fmaxf(ecnt[b], 1.f);
    for (int k = t; k < kD; k += 128) {
        emb[k]      = hsum[b * kD + k] / hc;
        emb[kD + k] = osum[b * kD + k] / oc;
    }
    for (int k = t; k < 32; k += 128) emb[2 * kD + k] = esum[b * 32 + k] / ec;
    __syncthreads();

    for (int head = 0; head < 2; head++) {
        const float* W  = head ? Wp2 : Wp1;
        const float* bb = head ? bp2 : bp1;
        float v = -3.0e38f;
        if (t < kC) {
            v = bb[t];
            for (int k = 0; k < 2 * kD + 32; k++) v += emb[k] * W[k * kC + t];
        }
        red[t] = v;
        __syncthreads();
        for (int s = 64; s > 0; s >>= 1) {
            if (t < s) red[t] = fmaxf(red[t], red[t + s]);
            __syncthreads();
        }
        float mx = red[0];
        __syncthreads();
        float ex = (t < kC) ? expf(v - mx) : 0.f;
        red[t] = ex;
        __syncthreads();
        for (int s = 64; s > 0; s >>= 1) {
            if (t < s) red[t] += red[t + s];
            __syncthreads();
        }
        float sm = red[0];
        __syncthreads();
        if (t < kC) out[(b * 2 + head) * kC + t] = ex / sm;
    }
}

// ---------------- launch ----------------
extern "C" void kernel_launch(void* const* d_in, const int* in_sizes, int n_in,
                              void* d_out, int out_size)
{
    const float* x_human = (const float*)d_in[0];
    const float* x_object = (const float*)d_in[1];
    const int* ei_ho = (const int*)d_in[2];
    const int* ei_oh = (const int*)d_in[3];
    const float* ea_ho = (const float*)d_in[4];
    const float* ea_oh = (const float*)d_in[5];
    const int* hbatch = (const int*)d_in[6];
    const int* obatch = (const int*)d_in[7];
    const float* Wsrc_ho = (const float*)d_in[8];
    const float* Wdst_ho = (const float*)d_in[9];
    const float* asrc_ho = (const float*)d_in[10];
    const float* adst_ho = (const float*)d_in[11];
    const float* Wedge_ho = (const float*)d_in[12];
    const float* aedge_ho = (const float*)d_in[13];
    const float* bias_ho = (const float*)d_in[14];
    const float* Wsrc_oh = (const float*)d_in[15];
    const float* Wdst_oh = (const float*)d_in[16];
    const float* asrc_oh = (const float*)d_in[17];
    const float* adst_oh = (const float*)d_in[18];
    const float* Wedge_oh = (const float*)d_in[19];
    const float* aedge_oh = (const float*)d_in[20];
    const float* bias_oh = (const float*)d_in[21];
    const float* W_emlp = (const float*)d_in[22];
    const float* b_emlp = (const float*)d_in[23];
    const float* W_p1 = (const float*)d_in[24];
    const float* b_p1 = (const float*)d_in[25];
    const float* W_p2 = (const float*)d_in[26];
    const float* b_p2 = (const float*)d_in[27];

    float *h0, *h1, *o0, *o1;
    float *aSho, *aDoh, *aDho, *aSoh, *vsrc, *vdst, *ced;
    float *hsum, *osum, *esum, *hcnt, *ocnt, *ecnt;
    __nv_bfloat16 *a0hi, *a0lo, *a1hi, *a1lo, *wTb;
    float2* ea2;
    int *srcs, *off, *cnt, *cur;
    cudaGetSymbolAddress((void**)&h0, g_h0);
    cudaGetSymbolAddress((void**)&h1, g_h1);
    cudaGetSymbolAddress((void**)&o0, g_o0);
    cudaGetSymbolAddress((void**)&o1, g_o1);
    cudaGetSymbolAddress((void**)&a0hi, g_a0hi);
    cudaGetSymbolAddress((void**)&a0lo, g_a0lo);
    cudaGetSymbolAddress((void**)&a1hi, g_a1hi);
    cudaGetSymbolAddress((void**)&a1lo, g_a1lo);
    cudaGetSymbolAddress((void**)&aSho, g_aSho);
    cudaGetSymbolAddress((void**)&aDoh, g_aDoh);
    cudaGetSymbolAddress((void**)&aDho, g_aDho);
    cudaGetSymbolAddress((void**)&aSoh, g_aSoh);
    cudaGetSymbolAddress((void**)&vsrc, g_vsrc);
    cudaGetSymbolAddress((void**)&vdst, g_vdst);
    cudaGetSymbolAddress((void**)&ced, g_cedge);
    cudaGetSymbolAddress((void**)&wTb, g_wTb);
    cudaGetSymbolAddress((void**)&cnt, g_cnt);
    cudaGetSymbolAddress((void**)&off, g_off);
    cudaGetSymbolAddress((void**)&cur, g_cursor);
    cudaGetSymbolAddress((void**)&srcs, g_srcs);
    cudaGetSymbolAddress((void**)&ea2, g_ea2);
    cudaGetSymbolAddress((void**)&hsum, g_hsum);
    cudaGetSymbolAddress((void**)&osum, g_osum);
    cudaGetSymbolAddress((void**)&esum, g_esum);
    cudaGetSymbolAddress((void**)&hcnt, g_hcnt);
    cudaGetSymbolAddress((void**)&ocnt, g_ocnt);
    cudaGetSymbolAddress((void**)&ecnt, g_ecnt);

    cudaFuncSetAttribute(k_gemm_mma, cudaFuncAttributeMaxDynamicSharedMemorySize, GEMM_SMEM);
    cudaFuncSetAttribute(k_pool_edges, cudaFuncAttributeMaxDynamicSharedMemorySize, PE_SMEM);

    const int EB = (kE + 255) / 256;
    const dim3 GEMM_GRID(2, (kNH + 127) / 128, 2);
    const int ZBLK = (2 * kNH + 255) / 256;

    // idx 0: prep (attention vectors + cnt zeroing)
    k_prep<<<16 + ZBLK, 256>>>(Wsrc_ho, asrc_ho, Wdst_ho, adst_ho, Wedge_ho, aedge_ho,
                               Wsrc_oh, asrc_oh, Wdst_oh, adst_oh, Wedge_oh, aedge_oh, cnt);
    // idx 1-3: CSR build
    k_hist<<<dim3(EB, 2), 256>>>(ei_ho + kE, ei_oh + kE, cnt);
    k_scan<<<dim3(NCHUNK, 2), 256>>>(cnt, off, cur);
    k_scatter<<<dim3(EB, 2), 256>>>(ei_ho + kE, ei_oh + kE, ei_ho, ei_oh,
                                    ea_ho, ea_oh, cur, srcs, ea2);

    // ---- 8 layers (idx 4 = matvec, idx 5 = aggregate -> ncu capture) ----
    const float* cur_h = x_human;
    const float* cur_o = x_object;
    for (int l = 0; l < kL; l++) {
        float* nh = (l & 1) ? h1 : h0;
        float* no = (l & 1) ? o1 : o0;

        k_matvec2_dual<<<(kNH + kNO) / 8, 256>>>(
            cur_h, cur_o,
            vsrc + (0 * kL + l) * kD, vdst + (1 * kL + l) * kD,
            vdst + (0 * kL + l) * kD, vsrc + (1 * kL + l) * kD,
            aSho, aDoh, aDho, aSoh);

        k_aggregate_dual<<<(kNO + kNH) / 8, 256>>>(
            off, srcs, ea2,
            aSho, aDho, cur_h, ced + (0 * kL + l) * 2, a0hi, a0lo,
            aSoh, aDoh, cur_o, ced + (1 * kL + l) * 2, a1hi, a1lo);

        if (l == 0)
            k_wprep<<<dim3(16, 64), dim3(32, 8)>>>(Wsrc_ho, Wsrc_oh);

        k_gemm_mma<<<GEMM_GRID, 512, GEMM_SMEM>>>(
            a0hi, a0lo, a1hi, a1lo,
            wTb + (long)(0 * kL + l) * 2 * kD * kD, wTb + (long)(1 * kL + l) * 2 * kD * kD,
            bias_ho + l * kD, bias_oh + l * kD,
            l ? cur_o : nullptr, l ? cur_h : nullptr,
            no, nh, kNO);

        cur_h = nh;
        cur_o = no;
    }

    // ---- pooling ----
    cudaMemsetAsync(hsum, 0, sizeof(float) * kB * kD);
    cudaMemsetAsync(osum, 0, sizeof(float) * kB * kD);
    cudaMemsetAsync(esum, 0, sizeof(float) * kB * 32);
    cudaMemsetAsync(hcnt, 0, sizeof(float) * kB);
    cudaMemsetAsync(ocnt, 0, sizeof(float) * kB);
    cudaMemsetAsync(ecnt, 0, sizeof(float) * kB);
    k_pool_nodes<<<(kNH + PCH - 1) / PCH, 256>>>(cur_h, hbatch, hsum, hcnt, kNH);
    k_pool_nodes<<<(kNO + PCH - 1) / PCH, 256>>>(cur_o, obatch, osum, ocnt, kNO);
    k_pool_edges<<<132, 256, PE_SMEM>>>(ea_ho, ei_ho, hbatch, W_emlp, b_emlp, esum, ecnt);

    // ---- classifier heads ----
    k_final<<<kB, 128>>>(hsum, hcnt, osum, ocnt, esum, ecnt,
                         W_p1, b_p1, W_p2, b_p2, (float*)d_out);
}

// round 13
// speedup vs baseline: 1.9845x; 1.1971x over previous
#include <cuda_runtime.h>
#include <cuda_bf16.h>
#include <cstdint>

static constexpr int kNH = 50000;
static constexpr int kNO = 50000;
static constexpr int kE  = 500000;
static constexpr int kD  = 256;
static constexpr int kL  = 8;
static constexpr int kB  = 512;
static constexpr int kC  = 117;
static constexpr int kPadRows = 128;

// ---------------- device scratch (static, no runtime alloc) ----------------
__device__ float g_h0[kNH * kD];
__device__ float g_h1[kNH * kD];
__device__ float g_o0[kNO * kD];
__device__ float g_o1[kNO * kD];

__device__ __nv_bfloat16 g_a0hi[(kNO + kPadRows) * kD];
__device__ __nv_bfloat16 g_a0lo[(kNO + kPadRows) * kD];
__device__ __nv_bfloat16 g_a1hi[(kNH + kPadRows) * kD];
__device__ __nv_bfloat16 g_a1lo[(kNH + kPadRows) * kD];

__device__ float g_aSho[kNH], g_aDoh[kNH], g_aDho[kNO], g_aSoh[kNO];

__device__ float g_vsrc[2 * kL * kD];
__device__ float g_vdst[2 * kL * kD];
__device__ float g_cedge[2 * kL * 2];

__device__ __nv_bfloat16 g_wTb[2 * kL * 2 * kD * kD];

static constexpr int SCHUNK = 4096;
static constexpr int NCHUNK = (kNH + SCHUNK - 1) / SCHUNK;  // 13

__device__ int g_cnt[2 * kNH];
__device__ int g_off[2 * (kNH + 1)];
__device__ int g_cursor[2 * kNH];

__device__ int    g_srcs[2 * kE];
__device__ float2 g_ea2[2 * kE];

// pooling: one contiguous block -> single memset
static constexpr int POOLN = 2 * kB * kD + kB * 32 + 3 * kB;
__device__ float g_pool[POOLN];

__device__ __forceinline__ uint32_t pack2(__nv_bfloat16 a, __nv_bfloat16 b) {
    return (uint32_t)__bfloat16_as_ushort(a) | ((uint32_t)__bfloat16_as_ushort(b) << 16);
}
__device__ __forceinline__ void cvt_split(float4 v, uint2& h, uint2& l) {
    __nv_bfloat16 hx = __float2bfloat16(v.x), hy = __float2bfloat16(v.y);
    __nv_bfloat16 hz = __float2bfloat16(v.z), hw = __float2bfloat16(v.w);
    __nv_bfloat16 lx = __float2bfloat16(v.x - __bfloat162float(hx));
    __nv_bfloat16 ly = __float2bfloat16(v.y - __bfloat162float(hy));
    __nv_bfloat16 lz = __float2bfloat16(v.z - __bfloat162float(hz));
    __nv_bfloat16 lw = __float2bfloat16(v.w - __bfloat162float(hw));
    h.x = pack2(hx, hy); h.y = pack2(hz, hw);
    l.x = pack2(lx, ly); l.y = pack2(lz, lw);
}
__device__ __forceinline__ uint32_t smem_u32(const void* p) {
    uint32_t a;
    asm("{ .reg .u64 t; cvta.to.shared.u64 t, %1; cvt.u32.u64 %0, t; }" : "=r"(a) : "l"(p));
    return a;
}
#define CP8(dst, src) \
    asm volatile("cp.async.ca.shared.global [%0], [%1], 8;" :: "r"(dst), "l"(src) : "memory")

// ============================================================================
// fused: per-layer attention-vector precompute + cnt zeroing
// ============================================================================
__global__ void k_prep(
    const float* __restrict__ Wsrc0, const float* __restrict__ asrc0,
    const float* __restrict__ Wdst0, const float* __restrict__ adst0,
    const float* __restrict__ Wedge0, const float* __restrict__ aedge0,
    const float* __restrict__ Wsrc1, const float* __restrict__ asrc1,
    const float* __restrict__ Wdst1, const float* __restrict__ adst1,
    const float* __restrict__ Wedge1, const float* __restrict__ aedge1,
    int* __restrict__ cnt)
{
    if (blockIdx.x >= 16) {
        int idx = (blockIdx.x - 16) * 256 + threadIdx.x;
        if (idx < 2 * kNH) cnt[idx] = 0;
        return;
    }
    int rel = blockIdx.x / kL;
    int l   = blockIdx.x % kL;
    const float* Wsrc  = rel ? Wsrc1  : Wsrc0;
    const float* asrc  = rel ? asrc1  : asrc0;
    const float* Wdst  = rel ? Wdst1  : Wdst0;
    const float* adst  = rel ? adst1  : adst0;
    const float* Wedge = rel ? Wedge1 : Wedge0;
    const float* aedge = rel ? aedge1 : aedge0;

    int i = threadIdx.x;
    float s1 = 0.f, s2 = 0.f;
    const float* wsr = Wsrc + (long)l * kD * kD + (long)i * kD;
    const float* wdr = Wdst + (long)l * kD * kD + (long)i * kD;
    const float* as  = asrc + l * kD;
    const float* ad  = adst + l * kD;
    for (int j = 0; j < kD; j++) { s1 += wsr[j] * as[j]; s2 += wdr[j] * ad[j]; }
    g_vsrc[(rel * kL + l) * kD + i] = s1;
    g_vdst[(rel * kL + l) * kD + i] = s2;
    if (i < 2) {
        float c = 0.f;
        const float* we = Wedge + (long)l * 2 * kD + (long)i * kD;
        const float* ae = aedge + l * kD;
        for (int j = 0; j < kD; j++) c += we[j] * ae[j];
        g_cedge[(rel * kL + l) * 2 + i] = c;
    }
}

// ---------------- transpose + bf16 hi/lo split of Wsrc weights ----------------
__global__ void k_wprep(const float* __restrict__ W_ho, const float* __restrict__ W_oh)
{
    int rl = blockIdx.x;
    int rel = rl >> 3;
    const float* W = (rel ? W_oh : W_ho) + (long)(rl & 7) * kD * kD;
    int tile = blockIdx.y;
    int tk = (tile & 7) * 32, tn = (tile >> 3) * 32;
    __shared__ float s[32][33];
    int tx = threadIdx.x, ty = threadIdx.y;
    for (int yy = ty; yy < 32; yy += 8)
        s[yy][tx] = W[(long)(tk + yy) * kD + tn + tx];
    __syncthreads();
    __nv_bfloat16* outHi = g_wTb + (long)rl * 2 * kD * kD;
    __nv_bfloat16* outLo = outHi + kD * kD;
    for (int yy = ty; yy < 32; yy += 8) {
        float v = s[tx][yy];
        __nv_bfloat16 h = __float2bfloat16(v);
        __nv_bfloat16 l = __float2bfloat16(v - __bfloat162float(h));
        outHi[(long)(tn + yy) * kD + tk + tx] = h;
        outLo[(long)(tn + yy) * kD + tk + tx] = l;
    }
}

// ---------------- CSR build ----------------
__global__ void k_hist(const int* __restrict__ d0, const int* __restrict__ d1,
                       int* __restrict__ cnt)
{
    int e = blockIdx.x * blockDim.x + threadIdx.x;
    if (e >= kE) return;
    int rel = blockIdx.y;
    const int* d = rel ? d1 : d0;
    atomicAdd(&cnt[rel * kNH + d[e]], 1);
}

__global__ void k_scan(const int* __restrict__ cnt, int* __restrict__ off,
                       int* __restrict__ cursor)
{
    int rel = blockIdx.y, ch = blockIdx.x;
    const int* cc = cnt + rel * kNH;
    int* oo = off + rel * (kNH + 1);
    int* uu = cursor + rel * kNH;
    int start = ch * SCHUNK;
    int n = min(SCHUNK, kNH - start);
    int t = threadIdx.x, lane = t & 31, wid = t >> 5;
    __shared__ int wsum[8];
    __shared__ int s_carry;

    int s = 0;
    for (int i = t; i < start; i += 256) s += cc[i];
#pragma unroll
    for (int o = 16; o > 0; o >>= 1) s += __shfl_xor_sync(0xffffffffu, s, o);
    if (lane == 0) wsum[wid] = s;
    __syncthreads();
    if (t == 0) {
        int tot = 0;
        for (int k = 0; k < 8; k++) tot += wsum[k];
        s_carry = tot;
    }
    __syncthreads();
    int carry = s_carry;
    __syncthreads();

    for (int b0 = 0; b0 < n; b0 += 256) {
        int i = start + b0 + t;
        int c = (b0 + t < n) ? cc[i] : 0;
        int v = c;
#pragma unroll
        for (int o = 1; o < 32; o <<= 1) {
            int u = __shfl_up_sync(0xffffffffu, v, o);
            if (lane >= o) v += u;
        }
        if (lane == 31) wsum[wid] = v;
        __syncthreads();
        int wpre = 0, btot = 0;
#pragma unroll
        for (int k = 0; k < 8; k++) {
            int ws = wsum[k];
            if (k < wid) wpre += ws;
            btot += ws;
        }
        int excl = carry + (v - c) + wpre;
        if (b0 + t < n) { oo[i] = excl; uu[i] = excl; }
        carry += btot;
        __syncthreads();
    }
    if (t == 0 && ch == 0) oo[kNH] = kE;
}

__global__ void k_scatter(const int* __restrict__ d0, const int* __restrict__ d1,
                          const int* __restrict__ s0, const int* __restrict__ s1,
                          const float* __restrict__ ea0, const float* __restrict__ ea1,
                          int* __restrict__ cur, int* __restrict__ srcs,
                          float2* __restrict__ ea2)
{
    int e = blockIdx.x * blockDim.x + threadIdx.x;
    if (e >= kE) return;
    int rel = blockIdx.y;
    const int* d = rel ? d1 : d0;
    const int* sp = rel ? s1 : s0;
    const float* ea = rel ? ea1 : ea0;
    int p = atomicAdd(&cur[rel * kNH + d[e]], 1);
    srcs[rel * kE + p] = sp[e];
    ea2[rel * kE + p] = make_float2(ea[2 * e], ea[2 * e + 1]);
}

// ---------------- fused dual matvec (float4) ----------------
__global__ void k_matvec2_dual(const float* __restrict__ xh, const float* __restrict__ xo,
                               const float* __restrict__ vh1, const float* __restrict__ vh2,
                               const float* __restrict__ vo1, const float* __restrict__ vo2,
                               float* __restrict__ aSho, float* __restrict__ aDoh,
                               float* __restrict__ aDho, float* __restrict__ aSoh)
{
    int gw = (blockIdx.x * blockDim.x + threadIdx.x) >> 5;
    int lane = threadIdx.x & 31;
    if (gw >= kNH + kNO) return;
    int rel = gw >= kNH;
    int w = rel ? gw - kNH : gw;
    const float* x  = rel ? xo  : xh;
    const float4* v1 = (const float4*)(rel ? vo1 : vh1);
    const float4* v2 = (const float4*)(rel ? vo2 : vh2);
    float* o1 = rel ? aDho : aSho;
    float* o2 = rel ? aSoh : aDoh;

    const float4* xr = (const float4*)(x + (long)w * kD);
    float4 xa = xr[lane], xb = xr[lane + 32];
    float4 va = v1[lane], vb = v1[lane + 32];
    float4 wa = v2[lane], wb = v2[lane + 32];
    float s1 = xa.x * va.x + xa.y * va.y + xa.z * va.z + xa.w * va.w
             + xb.x * vb.x + xb.y * vb.y + xb.z * vb.z + xb.w * vb.w;
    float s2 = xa.x * wa.x + xa.y * wa.y + xa.z * wa.z + xa.w * wa.w
             + xb.x * wb.x + xb.y * wb.y + xb.z * wb.z + xb.w * wb.w;
#pragma unroll
    for (int o = 16; o > 0; o >>= 1) {
        s1 += __shfl_xor_sync(0xffffffffu, s1, o);
        s2 += __shfl_xor_sync(0xffffffffu, s2, o);
    }
    if (lane == 0) { o1[w] = s1; o2[w] = s2; }
}

// ---------------- dual segment softmax + gather-aggregate; writes bf16 hi/lo ----------------
__global__ void k_aggregate_dual(
    const int* __restrict__ off, const int* __restrict__ srcs,
    const float2* __restrict__ ea2,
    const float* __restrict__ aS0, const float* __restrict__ aD0,
    const float* __restrict__ x0, const float* __restrict__ ced0,
    __nv_bfloat16* __restrict__ a0hi, __nv_bfloat16* __restrict__ a0lo,
    const float* __restrict__ aS1, const float* __restrict__ aD1,
    const float* __restrict__ x1, const float* __restrict__ ced1,
    __nv_bfloat16* __restrict__ a1hi, __nv_bfloat16* __restrict__ a1lo)
{
    int gw = (blockIdx.x * blockDim.x + threadIdx.x) >> 5;
    int lane = threadIdx.x & 31;
    if (gw >= kNO + kNH) return;
    int rel = gw >= kNO;
    int w = rel ? gw - kNO : gw;
    const int* o     = off + rel * (kNH + 1);
    const int* sc    = srcs + rel * kE;
    const float2* e2 = ea2 + rel * kE;
    const float* aS  = rel ? aS1 : aS0;
    const float* aD  = rel ? aD1 : aD0;
    const float* x   = rel ? x1 : x0;
    const float* ced = rel ? ced1 : ced0;
    __nv_bfloat16* ahi = rel ? a1hi : a0hi;
    __nv_bfloat16* alo = rel ? a1lo : a0lo;

    int beg = o[w], end = o[w + 1];
    int deg = end - beg;
    float c0 = ced[0], c1 = ced[1];
    float ad = aD[w];

    float4 acc0 = make_float4(0.f, 0.f, 0.f, 0.f);
    float4 acc1 = make_float4(0.f, 0.f, 0.f, 0.f);

    if (deg <= 128) {
        int sid[4];
        float ex[4];
        float m = -3.0e38f;
#pragma unroll
        for (int s = 0; s < 4; s++) {
            int i = beg + lane + 32 * s;
            bool ok = i < end;
            sid[s] = ok ? sc[i] : 0;
            float lg = -3.0e38f;
            if (ok) {
                float2 e = e2[i];
                lg = aS[sid[s]] + ad + c0 * e.x + c1 * e.y;
                lg = lg > 0.f ? lg : 0.2f * lg;
            }
            ex[s] = lg;
            m = fmaxf(m, lg);
        }
#pragma unroll
        for (int o2 = 16; o2 > 0; o2 >>= 1) m = fmaxf(m, __shfl_xor_sync(0xffffffffu, m, o2));

        float den = 0.f;
#pragma unroll
        for (int s = 0; s < 4; s++) {
            float e_ = (beg + lane + 32 * s < end) ? expf(ex[s] - m) : 0.f;
            ex[s] = e_;
            den += e_;
        }
#pragma unroll
        for (int o2 = 16; o2 > 0; o2 >>= 1) den += __shfl_xor_sync(0xffffffffu, den, o2);
        float inv = (den > 0.f) ? 1.f / den : 0.f;

#pragma unroll
        for (int s = 0; s < 4; s++) {
            int base = beg + 32 * s;
            int cnt = min(32, end - base);
            if (cnt <= 0) break;
            float wts = ex[s] * inv;
            for (int t = 0; t < cnt; t++) {
                float wt = __shfl_sync(0xffffffffu, wts, t);
                int sb   = __shfl_sync(0xffffffffu, sid[s], t);
                const float4* xr = (const float4*)(x + (long)sb * kD);
                float4 xa = xr[lane];
                float4 xb = xr[lane + 32];
                acc0.x += wt * xa.x; acc0.y += wt * xa.y;
                acc0.z += wt * xa.z; acc0.w += wt * xa.w;
                acc1.x += wt * xb.x; acc1.y += wt * xb.y;
                acc1.z += wt * xb.z; acc1.w += wt * xb.w;
            }
        }
    } else {
        float m = -3.0e38f;
        for (int i = beg + lane; i < end; i += 32) {
            float2 e = e2[i];
            float lg = aS[sc[i]] + ad + c0 * e.x + c1 * e.y;
            lg = lg > 0.f ? lg : 0.2f * lg;
            m = fmaxf(m, lg);
        }
#pragma unroll
        for (int o2 = 16; o2 > 0; o2 >>= 1) m = fmaxf(m, __shfl_xor_sync(0xffffffffu, m, o2));
        float den = 0.f;
        for (int i = beg + lane; i < end; i += 32) {
            float2 e = e2[i];
            float lg = aS[sc[i]] + ad + c0 * e.x + c1 * e.y;
            lg = lg > 0.f ? lg : 0.2f * lg;
            den += expf(lg - m);
        }
#pragma unroll
        for (int o2 = 16; o2 > 0; o2 >>= 1) den += __shfl_xor_sync(0xffffffffu, den, o2);
        float inv = (den > 0.f) ? 1.f / den : 0.f;
        for (int i = beg; i < end; i++) {
            float2 e = e2[i];
            int sb = sc[i];
            float lg = aS[sb] + ad + c0 * e.x + c1 * e.y;
            lg = lg > 0.f ? lg : 0.2f * lg;
            float wt = expf(lg - m) * inv;
            const float4* xr = (const float4*)(x + (long)sb * kD);
            float4 xa = xr[lane];
            float4 xb = xr[lane + 32];
            acc0.x += wt * xa.x; acc0.y += wt * xa.y;
            acc0.z += wt * xa.z; acc0.w += wt * xa.w;
            acc1.x += wt * xb.x; acc1.y += wt * xb.y;
            acc1.z += wt * xb.z; acc1.w += wt * xb.w;
        }
    }

    uint2 h0, l0, h1, l1;
    cvt_split(acc0, h0, l0);
    cvt_split(acc1, h1, l1);
    uint2* rh = (uint2*)(ahi + (long)w * kD);
    uint2* rl = (uint2*)(alo + (long)w * kD);
    rh[lane] = h0; rh[lane + 32] = h1;
    rl[lane] = l0; rl[lane + 32] = l1;
}

// ============================================================================
// mma.sync bf16 GEMM (3xBF16), cp.async double-buffered, 256 threads,
// __launch_bounds__(256,2) -> guaranteed 2 CTAs/SM. Warp tile 32M x 64N.
// ============================================================================
static constexpr int HSTRIDE = 40;
static constexpr int PLANEH = 128 * HSTRIDE;          // halfs per plane (5120)
static constexpr int BUFH = 4 * PLANEH;               // halfs per stage (20480 = 40KB)
static constexpr int PLB = PLANEH * 2;                // plane bytes (10240)
static constexpr int GEMM_SMEM = 2 * BUFH * 2;        // 81920 B

__device__ __forceinline__ void mma_bf16(float* c, const uint32_t* a, const uint32_t* b) {
    asm volatile(
        "mma.sync.aligned.m16n8k16.row.col.f32.bf16.bf16.f32 "
        "{%0,%1,%2,%3}, {%4,%5,%6,%7}, {%8,%9}, {%0,%1,%2,%3};\n"
        : "+f"(c[0]), "+f"(c[1]), "+f"(c[2]), "+f"(c[3])
        : "r"(a[0]), "r"(a[1]), "r"(a[2]), "r"(a[3]), "r"(b[0]), "r"(b[1]));
}

__global__ void __launch_bounds__(256, 2) k_gemm_mma(
    const __nv_bfloat16* __restrict__ A0hi, const __nv_bfloat16* __restrict__ A0lo,
    const __nv_bfloat16* __restrict__ A1hi, const __nv_bfloat16* __restrict__ A1lo,
    const __nv_bfloat16* __restrict__ WT0, const __nv_bfloat16* __restrict__ WT1,
    const float* __restrict__ bias0, const float* __restrict__ bias1,
    const float* __restrict__ prev0, const float* __restrict__ prev1,
    float* __restrict__ out0, float* __restrict__ out1, int M)
{
    extern __shared__ __nv_bfloat16 smh[];
    const uint32_t sb = smem_u32(smh);

    const int z = blockIdx.z;
    const __nv_bfloat16* Ahi = z ? A1hi : A0hi;
    const __nv_bfloat16* Alo = z ? A1lo : A0lo;
    const __nv_bfloat16* WT = z ? WT1 : WT0;
    const float* bias = z ? bias1 : bias0;
    const float* prev = z ? prev1 : prev0;
    float* out = z ? out1 : out0;

    const int tid = threadIdx.x;
    const int w = tid >> 5, lane = tid & 31;
    const int wm = w & 3, wn = w >> 2;            // 4x2 warp grid; warp = 32M x 64N
    const int grp = lane >> 2, qt = lane & 3;
    const int mBase = blockIdx.y * 128;
    const int nBase = blockIdx.x * 128;

    const __nv_bfloat16* WThi = WT + (long)nBase * kD;
    const __nv_bfloat16* WTlo = WT + (long)kD * kD + (long)nBase * kD;

    const int r0 = tid >> 3, q0 = tid & 7;        // r0: 0..31, q0: 0..7

    float acc[2][8][4];
#pragma unroll
    for (int i = 0; i < 2; i++)
#pragma unroll
        for (int j = 0; j < 8; j++)
#pragma unroll
            for (int q = 0; q < 4; q++) acc[i][j][q] = 0.f;

#define ISSUE(c, buf)                                                       \
    do {                                                                    \
        uint32_t base = sb + (uint32_t)(buf) * (BUFH * 2);                  \
        long ko = (long)(c) * 32 + q0 * 4;                                  \
        _Pragma("unroll")                                                   \
        for (int k = 0; k < 4; k++) {                                       \
            int r = r0 + 32 * k;                                            \
            uint32_t dOff = 2 * (r * HSTRIDE + q0 * 4);                     \
            long gA = (long)(mBase + r) * kD + ko;                          \
            long gB = (long)r * kD + ko;                                    \
            CP8(base + dOff, Ahi + gA);                                     \
            CP8(base + PLB + dOff, Alo + gA);                               \
            CP8(base + 2 * PLB + dOff, WThi + gB);                          \
            CP8(base + 3 * PLB + dOff, WTlo + gB);                          \
        }                                                                   \
        asm volatile("cp.async.commit_group;" ::: "memory");                \
    } while (0)

    ISSUE(0, 0);

#pragma unroll 1
    for (int c = 0; c < 8; c++) {
        const int cur = c & 1;
        if (c < 7) {
            ISSUE(c + 1, cur ^ 1);
            asm volatile("cp.async.wait_group 1;" ::: "memory");
        } else {
            asm volatile("cp.async.wait_group 0;" ::: "memory");
        }
        __syncthreads();

        const __nv_bfloat16* sAhi = smh + cur * BUFH;
        const __nv_bfloat16* sAlo = sAhi + PLANEH;
        const __nv_bfloat16* sBhi = sAhi + 2 * PLANEH;
        const __nv_bfloat16* sBlo = sAhi + 3 * PLANEH;
#pragma unroll
        for (int ks = 0; ks < 2; ks++) {
            int kb = ks * 16;
            uint32_t ahi[2][4], alo[2][4];
#pragma unroll
            for (int i = 0; i < 2; i++) {
                int ra = (wm * 32 + i * 16 + grp) * HSTRIDE + kb + qt * 2;
                ahi[i][0] = *(const uint32_t*)&sAhi[ra];
                ahi[i][1] = *(const uint32_t*)&sAhi[ra + 8 * HSTRIDE];
                ahi[i][2] = *(const uint32_t*)&sAhi[ra + 8];
                ahi[i][3] = *(const uint32_t*)&sAhi[ra + 8 * HSTRIDE + 8];
                alo[i][0] = *(const uint32_t*)&sAlo[ra];
                alo[i][1] = *(const uint32_t*)&sAlo[ra + 8 * HSTRIDE];
                alo[i][2] = *(const uint32_t*)&sAlo[ra + 8];
                alo[i][3] = *(const uint32_t*)&sAlo[ra + 8 * HSTRIDE + 8];
            }
#pragma unroll
            for (int jh = 0; jh < 2; jh++) {
                uint32_t bhi[4][2], blo[4][2];
#pragma unroll
                for (int jj = 0; jj < 4; jj++) {
                    int rb = (wn * 64 + (jh * 4 + jj) * 8 + grp) * HSTRIDE + kb + qt * 2;
                    bhi[jj][0] = *(const uint32_t*)&sBhi[rb];
                    bhi[jj][1] = *(const uint32_t*)&sBhi[rb + 8];
                    blo[jj][0] = *(const uint32_t*)&sBlo[rb];
                    blo[jj][1] = *(const uint32_t*)&sBlo[rb + 8];
                }
#pragma unroll
                for (int i = 0; i < 2; i++)
#pragma unroll
                    for (int jj = 0; jj < 4; jj++) {
                        mma_bf16(acc[i][jh * 4 + jj], ahi[i], bhi[jj]);
                        mma_bf16(acc[i][jh * 4 + jj], ahi[i], blo[jj]);
                        mma_bf16(acc[i][jh * 4 + jj], alo[i], bhi[jj]);
                    }
            }
        }
        __syncthreads();
    }
#undef ISSUE

#pragma unroll
    for (int i = 0; i < 2; i++) {
#pragma unroll
        for (int h = 0; h < 2; h++) {
            int row = mBase + wm * 32 + i * 16 + grp + h * 8;
            if (row >= M) continue;
#pragma unroll
            for (int j = 0; j < 8; j++) {
                int col = nBase + wn * 64 + j * 8 + qt * 2;
                float v0 = acc[i][j][h * 2 + 0] + bias[col];
                float v1 = acc[i][j][h * 2 + 1] + bias[col + 1];
                v0 = fmaxf(v0, 0.f);
                v1 = fmaxf(v1, 0.f);
                if (prev) {
                    float2 pv = *(const float2*)&prev[(long)row * kD + col];
                    v0 += pv.x; v1 += pv.y;
                }
                float2 o; o.x = v0; o.y = v1;
                *(float2*)&out[(long)row * kD + col] = o;
            }
        }
    }
}

// ---------------- pooling ----------------
__global__ void k_pool_nodes(const float* __restrict__ x, const int* __restrict__ batch,
                             float* __restrict__ sum, float* __restrict__ cnt, int N)
{
    long idx = (long)blockIdx.x * blockDim.x + threadIdx.x;
    if (idx >= (long)N * kD) return;
    int n = (int)(idx >> 8);
    int d = (int)(idx & 255);
    int b = batch[n];
    atomicAdd(&sum[b * kD + d], x[idx]);
    if (d == 0) atomicAdd(&cnt[b], 1.f);
}

static constexpr int PE_SMEM = (kB * 32 + kB) * 4;
__global__ void k_pool_edges(const float* __restrict__ ea, const int* __restrict__ src,
                             const int* __restrict__ hbatch,
                             const float* __restrict__ Wm, const float* __restrict__ bm,
                             float* __restrict__ esum, float* __restrict__ ecnt)
{
    extern __shared__ float sm[];
    float* ss = sm;
    float* sc = sm + kB * 32;
    for (int i = threadIdx.x; i < kB * 32 + kB; i += blockDim.x) sm[i] = 0.f;
    __syncthreads();
    for (int e = blockIdx.x * blockDim.x + threadIdx.x; e < kE; e += gridDim.x * blockDim.x) {
        float e0 = ea[2 * e], e1 = ea[2 * e + 1];
        int b = hbatch[src[e]];
        atomicAdd(&sc[b], 1.f);
#pragma unroll
        for (int j = 0; j < 32; j++) {
            float v = fmaxf(e0 * Wm[j] + e1 * Wm[32 + j] + bm[j], 0.f);
            atomicAdd(&ss[b * 32 + j], v);
        }
    }
    __syncthreads();
    for (int i = threadIdx.x; i < kB * 32; i += blockDim.x)
        if (ss[i] != 0.f) atomicAdd(&esum[i], ss[i]);
    for (int i = threadIdx.x; i < kB; i += blockDim.x)
        if (sc[i] != 0.f) atomicAdd(&ecnt[i], sc[i]);
}

// ---------------- final: graph emb -> 2 softmax heads ----------------
__global__ void k_final(const float* __restrict__ hsum, const float* __restrict__ hcnt,
                        const float* __restrict__ osum, const float* __restrict__ ocnt,
                        const float* __restrict__ esum, const float* __restrict__ ecnt,
                        const float* __restrict__ Wp1, const float* __restrict__ bp1,
                        const float* __restrict__ Wp2, const float* __restrict__ bp2,
                        float* __restrict__ out)
{
    __shared__ float emb[2 * kD + 32];
    __shared__ float red[128];
    int b = blockIdx.x, t = threadIdx.x;
    float hc = fmaxf(hcnt[b], 1.f), oc = fmaxf(ocnt[b], 1.f), ec = fmaxf(ecnt[b], 1.f);
    for (int k = t; k < kD; k += 128) {
        emb[k]      = hsum[b * kD + k] / hc;
        emb[kD + k] = osum[b * kD + k] / oc;
    }
    for (int k = t; k < 32; k += 128) emb[2 * kD + k] = esum[b * 32 + k] / ec;
    __syncthreads();

    for (int head = 0; head < 2; head++) {
        const float* W  = head ? Wp2 : Wp1;
        const float* bb = head ? bp2 : bp1;
        float v = -3.0e38f;
        if (t < kC) {
            v = bb[t];
            for (int k = 0; k < 2 * kD + 32; k++) v += emb[k] * W[k * kC + t];
        }
        red[t] = v;
        __syncthreads();
        for (int s = 64; s > 0; s >>= 1) {
            if (t < s) red[t] = fmaxf(red[t], red[t + s]);
            __syncthreads();
        }
        float mx = red[0];
        __syncthreads();
        float ex = (t < kC) ? expf(v - mx) : 0.f;
        red[t] = ex;
        __syncthreads();
        for (int s = 64; s > 0; s >>= 1) {
            if (t < s) red[t] += red[t + s];
            __syncthreads();
        }
        float sm = red[0];
        __syncthreads();
        if (t < kC) out[(b * 2 + head) * kC + t] = ex / sm;
    }
}

// ---------------- launch ----------------
extern "C" void kernel_launch(void* const* d_in, const int* in_sizes, int n_in,
                              void* d_out, int out_size)
{
    const float* x_human = (const float*)d_in[0];
    const float* x_object = (const float*)d_in[1];
    const int* ei_ho = (const int*)d_in[2];
    const int* ei_oh = (const int*)d_in[3];
    const float* ea_ho = (const float*)d_in[4];
    const float* ea_oh = (const float*)d_in[5];
    const int* hbatch = (const int*)d_in[6];
    const int* obatch = (const int*)d_in[7];
    const float* Wsrc_ho = (const float*)d_in[8];
    const float* Wdst_ho = (const float*)d_in[9];
    const float* asrc_ho = (const float*)d_in[10];
    const float* adst_ho = (const float*)d_in[11];
    const float* Wedge_ho = (const float*)d_in[12];
    const float* aedge_ho = (const float*)d_in[13];
    const float* bias_ho = (const float*)d_in[14];
    const float* Wsrc_oh = (const float*)d_in[15];
    const float* Wdst_oh = (const float*)d_in[16];
    const float* asrc_oh = (const float*)d_in[17];
    const float* adst_oh = (const float*)d_in[18];
    const float* Wedge_oh = (const float*)d_in[19];
    const float* aedge_oh = (const float*)d_in[20];
    const float* bias_oh = (const float*)d_in[21];
    const float* W_emlp = (const float*)d_in[22];
    const float* b_emlp = (const float*)d_in[23];
    const float* W_p1 = (const float*)d_in[24];
    const float* b_p1 = (const float*)d_in[25];
    const float* W_p2 = (const float*)d_in[26];
    const float* b_p2 = (const float*)d_in[27];

    float *h0, *h1, *o0, *o1;
    float *aSho, *aDoh, *aDho, *aSoh, *vsrc, *vdst, *ced, *pool;
    __nv_bfloat16 *a0hi, *a0lo, *a1hi, *a1lo, *wTb;
    float2* ea2;
    int *srcs, *off, *cnt, *cur;
    cudaGetSymbolAddress((void**)&h0, g_h0);
    cudaGetSymbolAddress((void**)&h1, g_h1);
    cudaGetSymbolAddress((void**)&o0, g_o0);
    cudaGetSymbolAddress((void**)&o1, g_o1);
    cudaGetSymbolAddress((void**)&a0hi, g_a0hi);
    cudaGetSymbolAddress((void**)&a0lo, g_a0lo);
    cudaGetSymbolAddress((void**)&a1hi, g_a1hi);
    cudaGetSymbolAddress((void**)&a1lo, g_a1lo);
    cudaGetSymbolAddress((void**)&aSho, g_aSho);
    cudaGetSymbolAddress((void**)&aDoh, g_aDoh);
    cudaGetSymbolAddress((void**)&aDho, g_aDho);
    cudaGetSymbolAddress((void**)&aSoh, g_aSoh);
    cudaGetSymbolAddress((void**)&vsrc, g_vsrc);
    cudaGetSymbolAddress((void**)&vdst, g_vdst);
    cudaGetSymbolAddress((void**)&ced, g_cedge);
    cudaGetSymbolAddress((void**)&wTb, g_wTb);
    cudaGetSymbolAddress((void**)&cnt, g_cnt);
    cudaGetSymbolAddress((void**)&off, g_off);
    cudaGetSymbolAddress((void**)&cur, g_cursor);
    cudaGetSymbolAddress((void**)&srcs, g_srcs);
    cudaGetSymbolAddress((void**)&ea2, g_ea2);
    cudaGetSymbolAddress((void**)&pool, g_pool);

    cudaFuncSetAttribute(k_gemm_mma, cudaFuncAttributeMaxDynamicSharedMemorySize, GEMM_SMEM);
    cudaFuncSetAttribute(k_pool_edges, cudaFuncAttributeMaxDynamicSharedMemorySize, PE_SMEM);

    const int EB = (kE + 255) / 256;
    const dim3 GEMM_GRID(2, (kNH + 127) / 128, 2);
    const int ZBLK = (2 * kNH + 255) / 256;

    k_prep<<<16 + ZBLK, 256>>>(Wsrc_ho, asrc_ho, Wdst_ho, adst_ho, Wedge_ho, aedge_ho,
                               Wsrc_oh, asrc_oh, Wdst_oh, adst_oh, Wedge_oh, aedge_oh, cnt);
    k_hist<<<dim3(EB, 2), 256>>>(ei_ho + kE, ei_oh + kE, cnt);
    k_scan<<<dim3(NCHUNK, 2), 256>>>(cnt, off, cur);
    k_scatter<<<dim3(EB, 2), 256>>>(ei_ho + kE, ei_oh + kE, ei_ho, ei_oh,
                                    ea_ho, ea_oh, cur, srcs, ea2);

    // ---- 8 layers ----
    const float* cur_h = x_human;
    const float* cur_o = x_object;
    for (int l = 0; l < kL; l++) {
        float* nh = (l & 1) ? h1 : h0;
        float* no = (l & 1) ? o1 : o0;

        k_matvec2_dual<<<(kNH + kNO) / 8, 256>>>(
            cur_h, cur_o,
            vsrc + (0 * kL + l) * kD, vdst + (1 * kL + l) * kD,
            vdst + (0 * kL + l) * kD, vsrc + (1 * kL + l) * kD,
            aSho, aDoh, aDho, aSoh);

        k_aggregate_dual<<<(kNO + kNH) / 8, 256>>>(
            off, srcs, ea2,
            aSho, aDho, cur_h, ced + (0 * kL + l) * 2, a0hi, a0lo,
            aSoh, aDoh, cur_o, ced + (1 * kL + l) * 2, a1hi, a1lo);

        if (l == 0)
            k_wprep<<<dim3(16, 64), dim3(32, 8)>>>(Wsrc_ho, Wsrc_oh);

        k_gemm_mma<<<GEMM_GRID, 256, GEMM_SMEM>>>(
            a0hi, a0lo, a1hi, a1lo,
            wTb + (long)(0 * kL + l) * 2 * kD * kD, wTb + (long)(1 * kL + l) * 2 * kD * kD,
            bias_ho + l * kD, bias_oh + l * kD,
            l ? cur_o : nullptr, l ? cur_h : nullptr,
            no, nh, kNO);

        cur_h = nh;
        cur_o = no;
    }

    // ---- pooling (single contiguous buffer, one memset) ----
    cudaMemsetAsync(pool, 0, sizeof(float) * POOLN);
    float* hsum = pool;
    float* osum = pool + kB * kD;
    float* esum = pool + 2 * kB * kD;
    float* hcnt = pool + 2 * kB * kD + kB * 32;
    float* ocnt = hcnt + kB;
    float* ecnt = ocnt + kB;
    k_pool_nodes<<<kNH, 256>>>(cur_h, hbatch, hsum, hcnt, kNH);
    k_pool_nodes<<<kNO, 256>>>(cur_o, obatch, osum, ocnt, kNO);
    k_pool_edges<<<132, 256, PE_SMEM>>>(ea_ho, ei_ho, hbatch, W_emlp, b_emlp, esum, ecnt);

    // ---- classifier heads ----
    k_final<<<kB, 128>>>(hsum, hcnt, osum, ocnt, esum, ecnt,
                         W_p1, b_p1, W_p2, b_p2, (float*)d_out);
}